// round 13
// baseline (speedup 1.0000x reference)
#include <cuda_runtime.h>
#include <cuda_bf16.h>
#include <cuda_fp16.h>
#include <cstdint>
#include <stdint.h>
#include <math.h>

#define DIMN   1024
#define NHEADS 16
#define HDIM   64
#define LORA_D 16
#define BB     4
#define TT     1024
#define MTOK   (BB*TT)   // 4096
#define KCATP  2048      // proj: 2-term fp16 split

// ---------------- scratch ----------------
__device__ float g_h[MTOK*48];
__device__ __half g_qcat[(size_t)MTOK*DIMN];   // qkv acts: single fp16 term
__device__ __half g_kcat[(size_t)MTOK*DIMN];
__device__ __half g_vcat[(size_t)MTOK*DIMN];
__device__ __half g_acat[(size_t)MTOK*KCATP];  // proj input [hi|lo], written by attention
__device__ __half g_wq[(size_t)DIMN*DIMN];
__device__ __half g_wk[(size_t)DIMN*DIMN];
__device__ __half g_wv[(size_t)DIMN*DIMN];
__device__ __half g_wp[(size_t)DIMN*DIMN];
__device__ __half g_qh[(size_t)MTOK*DIMN];     // [bh][t][64]
__device__ __half g_kh[(size_t)MTOK*DIMN];
__device__ __half g_vh[(size_t)MTOK*DIMN];
__device__ float2 g_rope[TT*32];               // (cos, sin) per (t, j)

// ---------------- asm helpers ----------------
__device__ __forceinline__ void cpa16(unsigned int d, const void* s) {
    asm volatile("cp.async.cg.shared.global [%0], [%1], 16;\n" :: "r"(d), "l"(s));
}
__device__ __forceinline__ void ldsm4(unsigned int a, unsigned int* r) {
    asm volatile("ldmatrix.sync.aligned.m8n8.x4.shared.b16 {%0,%1,%2,%3}, [%4];\n"
        : "=r"(r[0]), "=r"(r[1]), "=r"(r[2]), "=r"(r[3]) : "r"(a));
}
__device__ __forceinline__ void ldsm4t(unsigned int a, unsigned int* r) {
    asm volatile("ldmatrix.sync.aligned.m8n8.x4.trans.shared.b16 {%0,%1,%2,%3}, [%4];\n"
        : "=r"(r[0]), "=r"(r[1]), "=r"(r[2]), "=r"(r[3]) : "r"(a));
}
__device__ __forceinline__ void mmah(float* c, unsigned int a0, unsigned int a1,
                                     unsigned int a2, unsigned int a3,
                                     unsigned int b0, unsigned int b1) {
    asm volatile("mma.sync.aligned.m16n8k16.row.col.f32.f16.f16.f32 "
        "{%0,%1,%2,%3},{%4,%5,%6,%7},{%8,%9},{%0,%1,%2,%3};\n"
        : "+f"(c[0]), "+f"(c[1]), "+f"(c[2]), "+f"(c[3])
        : "r"(a0), "r"(a1), "r"(a2), "r"(a3), "r"(b0), "r"(b1));
}
__device__ __forceinline__ unsigned int ex2h2(unsigned int x) {
    unsigned int d;
    asm("ex2.approx.f16x2 %0, %1;" : "=r"(d) : "r"(x));
    return d;
}
__device__ __forceinline__ unsigned int cvt2h(float hi, float lo) {
    unsigned int d;
    asm("cvt.rn.f16x2.f32 %0, %1, %2;" : "=r"(d) : "f"(hi), "f"(lo));
    return d;
}

// ---------------- kernel 0: rope table ----------------
__global__ void __launch_bounds__(256) rope_tab_kernel() {
    const int idx = blockIdx.x * 256 + threadIdx.x;     // 32768
    const int t = idx >> 5, j = idx & 31;
    float theta = 1.0f / powf(10000.0f, (float)j * (1.0f / 32.0f));
    float ang = (float)t * theta;
    float sn, cs;
    sincosf(ang, &sn, &cs);
    g_rope[idx] = make_float2(cs, sn);
}

// ---------------- kernel 1: H = tanh(x @ Acat^T) ----------
__global__ void __launch_bounds__(256) lora_h_kernel(const float* __restrict__ x,
                                                     const float* __restrict__ qa,
                                                     const float* __restrict__ ka,
                                                     const float* __restrict__ va) {
    __shared__ float xs[8][DIMN];
    const int tok0 = blockIdx.x * 8;
    const int tid  = threadIdx.x;

    const float4* xg  = (const float4*)(x + (size_t)tok0 * DIMN);
    float4*       xs4 = (float4*)&xs[0][0];
#pragma unroll
    for (int i = 0; i < 8; i++) xs4[tid + i*256] = xg[tid + i*256];
    __syncthreads();

    const int warp = tid >> 5, lane = tid & 31;
#pragma unroll
    for (int jj = 0; jj < 6; jj++) {
        const int j = warp * 6 + jj;
        const float* a = (j < 16) ? (qa + j*DIMN)
                       : (j < 32) ? (ka + (j-16)*DIMN)
                                  : (va + (j-32)*DIMN);
        float acc[8];
#pragma unroll
        for (int t = 0; t < 8; t++) acc[t] = 0.f;
        for (int i = 0; i < 32; i++) {
            float av = a[lane + i*32];
#pragma unroll
            for (int t = 0; t < 8; t++) acc[t] += xs[t][lane + i*32] * av;
        }
#pragma unroll
        for (int off = 16; off; off >>= 1) {
#pragma unroll
            for (int t = 0; t < 8; t++)
                acc[t] += __shfl_xor_sync(0xffffffffu, acc[t], off);
        }
        if (lane == 0) {
#pragma unroll
            for (int t = 0; t < 8; t++)
                g_h[(size_t)(tok0 + t)*48 + j] = tanhf(acc[t]);
        }
    }
}

// ---------------- kernel 2: mod inputs -> fp16, 512 CTAs (16 tok x 512 dim tiles) ------
__global__ void __launch_bounds__(256) mod_input3_kernel(const float* __restrict__ x,
                                                         const float* __restrict__ qb, const float* __restrict__ ql,
                                                         const float* __restrict__ kb, const float* __restrict__ kl,
                                                         const float* __restrict__ vb, const float* __restrict__ vl) {
    const int tok0 = blockIdx.x * 16;
    const int d0   = blockIdx.y * 512;
    __shared__ float hs[16][48];
    const int tid = threadIdx.x;
    for (int i = tid; i < 16*48; i += 256) {
        int t = i / 48, j = i % 48;
        hs[t][j] = g_h[(size_t)(tok0 + t)*48 + j];
    }
    __syncthreads();

#pragma unroll
    for (int c = 0; c < 2; c++) {
        const int d = d0 + tid + c*256;
        float bq[LORA_D], bk[LORA_D], bv[LORA_D];
        const float4* qrow = (const float4*)(qb + (size_t)d * LORA_D);
        const float4* krow = (const float4*)(kb + (size_t)d * LORA_D);
        const float4* vrow = (const float4*)(vb + (size_t)d * LORA_D);
#pragma unroll
        for (int q4 = 0; q4 < 4; q4++) {
            float4 w;
            w = qrow[q4]; bq[q4*4+0]=w.x; bq[q4*4+1]=w.y; bq[q4*4+2]=w.z; bq[q4*4+3]=w.w;
            w = krow[q4]; bk[q4*4+0]=w.x; bk[q4*4+1]=w.y; bk[q4*4+2]=w.z; bk[q4*4+3]=w.w;
            w = vrow[q4]; bv[q4*4+0]=w.x; bv[q4*4+1]=w.y; bv[q4*4+2]=w.z; bv[q4*4+3]=w.w;
        }
        const float lq = ql[d], lk = kl[d], lv = vl[d];
        float xprev = ((tok0 % TT) == 0) ? 0.f : x[(size_t)(tok0 - 1)*DIMN + d];
#pragma unroll
        for (int t = 0; t < 16; t++) {
            float xv = x[(size_t)(tok0 + t)*DIMN + d];
            float rq = lq, rk = lk, rv = lv;
#pragma unroll
            for (int j = 0; j < LORA_D; j++) {
                rq += hs[t][j]      * bq[j];
                rk += hs[t][16 + j] * bk[j];
                rv += hs[t][32 + j] * bv[j];
            }
            const float dx = xprev - xv;
            const size_t o = (size_t)(tok0 + t)*DIMN + d;
            g_qcat[o] = __float2half_rn(xv + dx*rq);
            g_kcat[o] = __float2half_rn(xv + dx*rk);
            g_vcat[o] = __float2half_rn(xv + dx*rv);
            xprev = xv;
        }
    }
}

// ---------------- kernel 2c: all 4 weights -> fp16 ----------------
__global__ void __launch_bounds__(256) split_w4_kernel(const float* __restrict__ qw,
                                                       const float* __restrict__ kw,
                                                       const float* __restrict__ vw,
                                                       const float* __restrict__ pw) {
    const int which = blockIdx.y;
    const float* in = (which == 0) ? qw : (which == 1) ? kw : (which == 2) ? vw : pw;
    __half* out = (which == 0) ? g_wq : (which == 1) ? g_wk : (which == 2) ? g_wv : g_wp;
    const int idx = blockIdx.x * 256 + threadIdx.x;
    out[idx] = __float2half_rn(in[idx]);
}

// ---------------- GEMM body: 256x128 tile, 3-stage ----------------
// MODE 0: fp32 C store (+bias).  MODE 1: fused RoPE/cvt fp16 store to OH in [bh][t][64]
#define GSTAGE 49152
#define GSMEM  (3*GSTAGE)

template<int KACT, int NIT, int MODE>
__device__ __forceinline__ void gemm_body(const __half* __restrict__ A,
                                          const __half* __restrict__ W,
                                          const float* __restrict__ bias,
                                          float* __restrict__ C,
                                          __half* __restrict__ OH,
                                          int do_rope,
                                          char* smem, int bx, int by) {
    const unsigned int su = (unsigned int)__cvta_generic_to_shared(smem);
    const int tid  = threadIdx.x;
    const int lane = tid & 31, warp = tid >> 5;
    const int wm = warp >> 1, wn = warp & 1;
    const int m0 = by * 256, n0 = bx * 128;

    float acc[4][8][4];
#pragma unroll
    for (int i = 0; i < 4; i++)
#pragma unroll
        for (int j = 0; j < 8; j++)
#pragma unroll
            for (int e = 0; e < 4; e++) acc[i][j][e] = 0.f;

    const int crow = tid >> 3;
    const int cc   = tid & 7;

    auto issue = [&](int s) {
        const int k0 = s * 64;
        const int kw = k0 & 1023;
        const unsigned int base = su + (unsigned int)((s % 3) * GSTAGE);
#pragma unroll
        for (int e = 0; e < 8; e++) {
            const int row = crow + e * 32;
            const unsigned int sw = (unsigned int)((cc ^ (row & 7)) << 4);
            cpa16(base + row*128 + sw, A + (size_t)(m0 + row)*KACT + k0 + cc*8);
        }
#pragma unroll
        for (int e = 0; e < 4; e++) {
            const int row = crow + e * 32;
            const unsigned int sw = (unsigned int)((cc ^ (row & 7)) << 4);
            cpa16(base + 32768 + row*128 + sw, W + (size_t)(n0 + row)*DIMN + kw + cc*8);
        }
        asm volatile("cp.async.commit_group;\n");
    };

    issue(0);
    issue(1);

    const int krow = lane & 15;
    const int hi16 = lane >> 4;

    for (int it = 0; it < NIT; it++) {
        if (it < NIT-1) asm volatile("cp.async.wait_group 1;\n");
        else            asm volatile("cp.async.wait_group 0;\n");
        __syncthreads();
        if (it + 2 < NIT) issue(it + 2);

        const unsigned int Ab = su + (unsigned int)((it % 3) * GSTAGE);
        const unsigned int Wb = Ab + 32768;

#pragma unroll
        for (int ks = 0; ks < 4; ks++) {
            unsigned int a[4][4], b[4][4];
#pragma unroll
            for (int im = 0; im < 4; im++) {
                const int row = wm*64 + im*16 + krow;
                ldsm4(Ab + (unsigned int)(row*128 + (((2*ks + hi16) ^ (row & 7)) << 4)), a[im]);
            }
#pragma unroll
            for (int jn = 0; jn < 4; jn++) {
                const int row = wn*64 + jn*16 + krow;
                ldsm4(Wb + (unsigned int)(row*128 + (((2*ks + hi16) ^ (row & 7)) << 4)), b[jn]);
            }
#pragma unroll
            for (int im = 0; im < 4; im++)
#pragma unroll
                for (int j8 = 0; j8 < 8; j8++) {
                    const int jn = j8 >> 1, p = j8 & 1;
                    mmah(acc[im][j8], a[im][0], a[im][1], a[im][2], a[im][3],
                         b[jn][p], b[jn][2 + p]);
                }
        }
    }

    if (MODE == 0) {
#pragma unroll
        for (int im = 0; im < 4; im++) {
            const int r0 = m0 + wm*64 + im*16 + (lane >> 2);
#pragma unroll
            for (int j8 = 0; j8 < 8; j8++) {
                const int col = n0 + wn*64 + j8*8 + 2*(lane & 3);
                float b0 = 0.f, b1 = 0.f;
                if (bias) { b0 = bias[col]; b1 = bias[col + 1]; }
                *(float2*)&C[(size_t)r0*1024 + col]       = make_float2(acc[im][j8][0] + b0, acc[im][j8][1] + b1);
                *(float2*)&C[(size_t)(r0 + 8)*1024 + col] = make_float2(acc[im][j8][2] + b0, acc[im][j8][3] + b1);
            }
        }
    } else {
        const int head = bx*2 + wn;                     // 2 heads per N-tile
#pragma unroll
        for (int im = 0; im < 4; im++) {
            const int r0 = m0 + wm*64 + im*16 + (lane >> 2);
            const int b = r0 >> 10, t0 = r0 & 1023, t1 = t0 + 8;
            const size_t d0 = ((size_t)(b*16 + head)*TT + t0)*HDIM;
            const size_t d1 = d0 + 8*HDIM;
            if (do_rope) {
#pragma unroll
                for (int j8 = 0; j8 < 4; j8++) {
                    const int hd = j8*8 + 2*(lane & 3);
                    const float2 ca0 = g_rope[t0*32 + hd];
                    const float2 cb0 = g_rope[t0*32 + hd + 1];
                    const float2 ca1 = g_rope[t1*32 + hd];
                    const float2 cb1 = g_rope[t1*32 + hd + 1];
                    const float xr0 = acc[im][j8][0],   xi0 = acc[im][j8+4][0];
                    const float xr1 = acc[im][j8][1],   xi1 = acc[im][j8+4][1];
                    const float xr2 = acc[im][j8][2],   xi2 = acc[im][j8+4][2];
                    const float xr3 = acc[im][j8][3],   xi3 = acc[im][j8+4][3];
                    *(__half2*)&OH[d0 + hd] = __halves2half2(
                        __float2half_rn(xr0*ca0.x - xi0*ca0.y),
                        __float2half_rn(xr1*cb0.x - xi1*cb0.y));
                    *(__half2*)&OH[d0 + hd + 32] = __halves2half2(
                        __float2half_rn(xr0*ca0.y + xi0*ca0.x),
                        __float2half_rn(xr1*cb0.y + xi1*cb0.x));
                    *(__half2*)&OH[d1 + hd] = __halves2half2(
                        __float2half_rn(xr2*ca1.x - xi2*ca1.y),
                        __float2half_rn(xr3*cb1.x - xi3*cb1.y));
                    *(__half2*)&OH[d1 + hd + 32] = __halves2half2(
                        __float2half_rn(xr2*ca1.y + xi2*ca1.x),
                        __float2half_rn(xr3*cb1.y + xi3*cb1.x));
                }
            } else {
#pragma unroll
                for (int j8 = 0; j8 < 8; j8++) {
                    const int hd = j8*8 + 2*(lane & 3);
                    *(__half2*)&OH[d0 + hd] = __halves2half2(
                        __float2half_rn(acc[im][j8][0]), __float2half_rn(acc[im][j8][1]));
                    *(__half2*)&OH[d1 + hd] = __halves2half2(
                        __float2half_rn(acc[im][j8][2]), __float2half_rn(acc[im][j8][3]));
                }
            }
        }
    }
}

// batched q/k/v GEMM (single-term, K=1024) with fused RoPE/cvt epilogue
__global__ void __launch_bounds__(256, 1) gemm_qkv_kernel() {
    extern __shared__ char smem[];
    const int z = blockIdx.z;
    const __half* A = (z == 0) ? g_qcat : (z == 1) ? g_kcat : g_vcat;
    const __half* W = (z == 0) ? g_wq   : (z == 1) ? g_wk   : g_wv;
    __half*      O = (z == 0) ? g_qh   : (z == 1) ? g_kh   : g_vh;
    gemm_body<DIMN, 16, 1>(A, W, nullptr, nullptr, O, (z < 2) ? 1 : 0,
                           smem, blockIdx.x, blockIdx.y);
}

// proj GEMM (2-term, K=2048)
__global__ void __launch_bounds__(256, 1) gemm_proj_kernel(const float* __restrict__ bias,
                                                           float* __restrict__ out) {
    extern __shared__ char smem[];
    gemm_body<KCATP, 32, 0>(g_acat, g_wp, bias, out, nullptr, 0,
                            smem, blockIdx.x, blockIdx.y);
}

// ---------------- kernel 5: tensor-core causal flash attention (1-seg QK, 1-term PV) --------
#define ATTN_SMEM 40960

__global__ void __launch_bounds__(128, 3) attn_mma_kernel() {
    extern __shared__ char smx[];
    const unsigned int su = (unsigned int)__cvta_generic_to_shared(smx);
    const int tid = threadIdx.x, lane = tid & 31, warp = tid >> 5;
    const int bx = blockIdx.x;
    const int qt = 15 - (bx >> 6);
    const int bh = bx & 63;
    const int q0 = qt * 64;
    const int nk = qt + 1;
    const size_t hb = (size_t)bh * (TT * HDIM);

    auto ldt = [&](unsigned int dstBase, const __half* g, int row0) {
#pragma unroll
        for (int e2 = 0; e2 < 4; e2++) {
            int idx = tid + e2*128;
            int r = idx >> 3, ch = idx & 7;
            cpa16(dstBase + (unsigned int)(r*128 + ((ch ^ (r & 7)) << 4)),
                  g + hb + (size_t)(row0 + r)*HDIM + ch*8);
        }
    };
    auto issue_kv = [&](int kt) {
        unsigned int base = su + 8192u + (unsigned int)((kt & 1) * 16384);
        ldt(base,         g_kh, kt*64);
        ldt(base + 8192u, g_vh, kt*64);
        asm volatile("cp.async.commit_group;\n");
    };

    ldt(su, g_qh, q0);
    asm volatile("cp.async.commit_group;\n");
    issue_kv(0);
    if (nk > 1) { issue_kv(1); asm volatile("cp.async.wait_group 1;\n"); }
    else        {              asm volatile("cp.async.wait_group 0;\n"); }
    __syncthreads();

    const int hi16 = lane >> 4;
    const int krow = lane & 15;
    const int wrow = warp*16 + (lane >> 2);

    unsigned int aq[4][4];
    {
        const int qrow = warp*16 + krow;
#pragma unroll
        for (int ck = 0; ck < 4; ck++)
            ldsm4(su + (unsigned int)(qrow*128 + (((2*ck + hi16) ^ (qrow & 7)) << 4)), aq[ck]);
    }

    float oacc[8][4], lacc[4];
#pragma unroll
    for (int j = 0; j < 8; j++)
#pragma unroll
        for (int e = 0; e < 4; e++) oacc[j][e] = 0.f;
#pragma unroll
    for (int e = 0; e < 4; e++) lacc[e] = 0.f;
    float m0 = -1e30f, m1 = -1e30f;

    const unsigned int ONES = 0x3C003C00u;

    for (int kt = 0; kt < nk; kt++) {
        const unsigned int sb = su + 8192u + (unsigned int)((kt & 1) * 16384);

        float c[8][4];
#pragma unroll
        for (int j = 0; j < 8; j++)
#pragma unroll
            for (int e = 0; e < 4; e++) c[j][e] = 0.f;

        // ---- S = Qh · Kh^T ----
#pragma unroll
        for (int ck = 0; ck < 4; ck++) {
#pragma unroll
            for (int g = 0; g < 4; g++) {
                unsigned int bq[4];
                const int row = g*16 + krow;
                ldsm4(sb + (unsigned int)(row*128 + (((2*ck + hi16) ^ (row & 7)) << 4)), bq);
                mmah(c[2*g],   aq[ck][0], aq[ck][1], aq[ck][2], aq[ck][3], bq[0], bq[2]);
                mmah(c[2*g+1], aq[ck][0], aq[ck][1], aq[ck][2], aq[ck][3], bq[1], bq[3]);
            }
        }

        const float alpha = 0.18033688011112042f;   // 0.125 * log2(e)
#pragma unroll
        for (int j = 0; j < 8; j++) {
            c[j][0] *= alpha; c[j][1] *= alpha; c[j][2] *= alpha; c[j][3] *= alpha;
        }
        if (kt == qt) {
#pragma unroll
            for (int j = 0; j < 8; j++) {
                const int cb = 8*j + 2*(lane & 3);
                if (cb     > wrow)     c[j][0] = -30000.f;
                if (cb + 1 > wrow)     c[j][1] = -30000.f;
                if (cb     > wrow + 8) c[j][2] = -30000.f;
                if (cb + 1 > wrow + 8) c[j][3] = -30000.f;
            }
        }
        float ml0 = -1e30f, ml1 = -1e30f;
#pragma unroll
        for (int j = 0; j < 8; j++) {
            ml0 = fmaxf(ml0, fmaxf(c[j][0], c[j][1]));
            ml1 = fmaxf(ml1, fmaxf(c[j][2], c[j][3]));
        }
#pragma unroll
        for (int off = 1; off <= 2; off <<= 1) {
            ml0 = fmaxf(ml0, __shfl_xor_sync(0xffffffffu, ml0, off));
            ml1 = fmaxf(ml1, __shfl_xor_sync(0xffffffffu, ml1, off));
        }
        const float mn0 = fmaxf(m0, ml0), mn1 = fmaxf(m1, ml1);
        const float cr0 = exp2f(m0 - mn0), cr1 = exp2f(m1 - mn1);
        m0 = mn0; m1 = mn1;

        unsigned int pf[2][8];
#pragma unroll
        for (int j = 0; j < 8; j++) {
            pf[0][j] = ex2h2(cvt2h(c[j][1] - m0, c[j][0] - m0));
            pf[1][j] = ex2h2(cvt2h(c[j][3] - m1, c[j][2] - m1));
        }
#pragma unroll
        for (int j = 0; j < 8; j++) {
            oacc[j][0] *= cr0; oacc[j][1] *= cr0;
            oacc[j][2] *= cr1; oacc[j][3] *= cr1;
        }
        lacc[0] *= cr0; lacc[1] *= cr0; lacc[2] *= cr1; lacc[3] *= cr1;

        // ---- O += P Vh, l += P @ ones ----
        const unsigned int Vb = sb + 8192u;
#pragma unroll
        for (int kc = 0; kc < 4; kc++) {
            const unsigned int a0 = pf[0][2*kc],   a1 = pf[1][2*kc];
            const unsigned int a2 = pf[0][2*kc+1], a3 = pf[1][2*kc+1];
            mmah(lacc, a0, a1, a2, a3, ONES, ONES);
            const int rbase = kc*16 + krow;
#pragma unroll
            for (int jj = 0; jj < 4; jj++) {
                unsigned int bv[4];
                ldsm4t(Vb + (unsigned int)(rbase*128 + (((2*jj + hi16) ^ (rbase & 7)) << 4)), bv);
                mmah(oacc[2*jj],   a0, a1, a2, a3, bv[0], bv[1]);
                mmah(oacc[2*jj+1], a0, a1, a2, a3, bv[2], bv[3]);
            }
        }

        if (kt + 1 < nk) {
            __syncthreads();
            if (kt + 2 < nk) {
                issue_kv(kt + 2);
                asm volatile("cp.async.wait_group 1;\n");
            } else {
                asm volatile("cp.async.wait_group 0;\n");
            }
            __syncthreads();
        }
    }

    // ---- epilogue: write fp16 [hi|lo] into g_acat ([tok][2048]) ----
    const float inv0 = 1.f / lacc[0];
    const float inv1 = 1.f / lacc[2];
    const int b = bh >> 4, h = bh & 15;
    const size_t tok0 = (size_t)b*TT + q0 + wrow;
#pragma unroll
    for (int j = 0; j < 8; j++) {
        const int col = 8*j + 2*(lane & 3);
        float a0 = oacc[j][0]*inv0, a1 = oacc[j][1]*inv0;
        float a2 = oacc[j][2]*inv1, a3 = oacc[j][3]*inv1;
        __half h0 = __float2half_rn(a0), h1 = __float2half_rn(a1);
        __half h2 = __float2half_rn(a2), h3 = __float2half_rn(a3);
        __half l0 = __float2half_rn(a0 - __half2float(h0));
        __half l1 = __float2half_rn(a1 - __half2float(h1));
        __half l2 = __float2half_rn(a2 - __half2float(h2));
        __half l3 = __float2half_rn(a3 - __half2float(h3));
        size_t base0 = tok0*KCATP + h*HDIM + col;
        size_t base1 = (tok0 + 8)*KCATP + h*HDIM + col;
        *(__half2*)&g_acat[base0]        = __halves2half2(h0, h1);
        *(__half2*)&g_acat[base0 + 1024] = __halves2half2(l0, l1);
        *(__half2*)&g_acat[base1]        = __halves2half2(h2, h3);
        *(__half2*)&g_acat[base1 + 1024] = __halves2half2(l2, l3);
    }
}

// ---------------- launch ----------------
extern "C" void kernel_launch(void* const* d_in, const int* in_sizes, int n_in,
                              void* d_out, int out_size) {
    const float* x      = (const float*)d_in[0];
    const float* q_w    = (const float*)d_in[1];
    const float* k_w    = (const float*)d_in[2];
    const float* v_w    = (const float*)d_in[3];
    const float* q_a    = (const float*)d_in[4];
    const float* q_b    = (const float*)d_in[5];
    const float* q_l    = (const float*)d_in[6];
    const float* k_a    = (const float*)d_in[7];
    const float* k_b    = (const float*)d_in[8];
    const float* k_l    = (const float*)d_in[9];
    const float* v_a    = (const float*)d_in[10];
    const float* v_b    = (const float*)d_in[11];
    const float* v_l    = (const float*)d_in[12];
    const float* proj_w = (const float*)d_in[13];
    const float* proj_b = (const float*)d_in[14];
    float* out = (float*)d_out;

    cudaFuncSetAttribute(gemm_qkv_kernel,
                         cudaFuncAttributeMaxDynamicSharedMemorySize, GSMEM);
    cudaFuncSetAttribute(gemm_proj_kernel,
                         cudaFuncAttributeMaxDynamicSharedMemorySize, GSMEM);
    cudaFuncSetAttribute(attn_mma_kernel,
                         cudaFuncAttributeMaxDynamicSharedMemorySize, ATTN_SMEM);

    rope_tab_kernel<<<(TT*32)/256, 256>>>();
    split_w4_kernel<<<dim3((DIMN*DIMN)/256, 4), 256>>>(q_w, k_w, v_w, proj_w);
    lora_h_kernel<<<MTOK/8, 256>>>(x, q_a, k_a, v_a);
    mod_input3_kernel<<<dim3(MTOK/16, 2), 256>>>(x, q_b, q_l, k_b, k_l, v_b, v_l);

    gemm_qkv_kernel<<<dim3(8, 16, 3), 256, GSMEM>>>();

    attn_mma_kernel<<<1024, 128, ATTN_SMEM>>>();

    gemm_proj_kernel<<<dim3(8, 16), 256, GSMEM>>>(proj_b, out);
}

// round 14
// speedup vs baseline: 2.3312x; 2.3312x over previous
#include <cuda_runtime.h>
#include <cuda_bf16.h>
#include <cuda_fp16.h>
#include <cstdint>
#include <stdint.h>
#include <math.h>

#define DIMN   1024
#define NHEADS 16
#define HDIM   64
#define LORA_D 16
#define BB     4
#define TT     1024
#define MTOK   (BB*TT)   // 4096
#define KCATP  2048      // proj: 2-term fp16 split

// ---------------- scratch ----------------
__device__ float g_h[MTOK*48];
__device__ __half g_qcat[(size_t)MTOK*DIMN];   // qkv acts: single fp16 term
__device__ __half g_kcat[(size_t)MTOK*DIMN];
__device__ __half g_vcat[(size_t)MTOK*DIMN];
__device__ __half g_acat[(size_t)MTOK*KCATP];  // proj input [hi|lo], written by attention
__device__ __half g_wq[(size_t)DIMN*DIMN];
__device__ __half g_wk[(size_t)DIMN*DIMN];
__device__ __half g_wv[(size_t)DIMN*DIMN];
__device__ __half g_wp[(size_t)DIMN*DIMN];
__device__ __half g_qh[(size_t)MTOK*DIMN];     // [bh][t][64]
__device__ __half g_kh[(size_t)MTOK*DIMN];
__device__ __half g_vh[(size_t)MTOK*DIMN];
__device__ float2 g_rope[TT*32];               // (cos, sin) per (t, j)

// ---------------- asm helpers ----------------
__device__ __forceinline__ void cpa16(unsigned int d, const void* s) {
    asm volatile("cp.async.cg.shared.global [%0], [%1], 16;\n" :: "r"(d), "l"(s));
}
__device__ __forceinline__ void ldsm4(unsigned int a, unsigned int* r) {
    asm volatile("ldmatrix.sync.aligned.m8n8.x4.shared.b16 {%0,%1,%2,%3}, [%4];\n"
        : "=r"(r[0]), "=r"(r[1]), "=r"(r[2]), "=r"(r[3]) : "r"(a));
}
__device__ __forceinline__ void ldsm4t(unsigned int a, unsigned int* r) {
    asm volatile("ldmatrix.sync.aligned.m8n8.x4.trans.shared.b16 {%0,%1,%2,%3}, [%4];\n"
        : "=r"(r[0]), "=r"(r[1]), "=r"(r[2]), "=r"(r[3]) : "r"(a));
}
__device__ __forceinline__ void mmah(float* c, unsigned int a0, unsigned int a1,
                                     unsigned int a2, unsigned int a3,
                                     unsigned int b0, unsigned int b1) {
    asm volatile("mma.sync.aligned.m16n8k16.row.col.f32.f16.f16.f32 "
        "{%0,%1,%2,%3},{%4,%5,%6,%7},{%8,%9},{%0,%1,%2,%3};\n"
        : "+f"(c[0]), "+f"(c[1]), "+f"(c[2]), "+f"(c[3])
        : "r"(a0), "r"(a1), "r"(a2), "r"(a3), "r"(b0), "r"(b1));
}
__device__ __forceinline__ unsigned int ex2h2(unsigned int x) {
    unsigned int d;
    asm("ex2.approx.f16x2 %0, %1;" : "=r"(d) : "r"(x));
    return d;
}
__device__ __forceinline__ unsigned int cvt2h(float hi, float lo) {
    unsigned int d;
    asm("cvt.rn.f16x2.f32 %0, %1, %2;" : "=r"(d) : "f"(hi), "f"(lo));
    return d;
}

// ---------------- kernel 0: rope table ----------------
__global__ void __launch_bounds__(256) rope_tab_kernel() {
    const int idx = blockIdx.x * 256 + threadIdx.x;     // 32768
    const int t = idx >> 5, j = idx & 31;
    float theta = 1.0f / powf(10000.0f, (float)j * (1.0f / 32.0f));
    float ang = (float)t * theta;
    float sn, cs;
    sincosf(ang, &sn, &cs);
    g_rope[idx] = make_float2(cs, sn);
}

// ---------------- kernel 1: H = tanh(x @ Acat^T) ----------
__global__ void __launch_bounds__(256) lora_h_kernel(const float* __restrict__ x,
                                                     const float* __restrict__ qa,
                                                     const float* __restrict__ ka,
                                                     const float* __restrict__ va) {
    __shared__ float xs[8][DIMN];
    const int tok0 = blockIdx.x * 8;
    const int tid  = threadIdx.x;

    const float4* xg  = (const float4*)(x + (size_t)tok0 * DIMN);
    float4*       xs4 = (float4*)&xs[0][0];
#pragma unroll
    for (int i = 0; i < 8; i++) xs4[tid + i*256] = xg[tid + i*256];
    __syncthreads();

    const int warp = tid >> 5, lane = tid & 31;
#pragma unroll
    for (int jj = 0; jj < 6; jj++) {
        const int j = warp * 6 + jj;
        const float* a = (j < 16) ? (qa + j*DIMN)
                       : (j < 32) ? (ka + (j-16)*DIMN)
                                  : (va + (j-32)*DIMN);
        float acc[8];
#pragma unroll
        for (int t = 0; t < 8; t++) acc[t] = 0.f;
        for (int i = 0; i < 32; i++) {
            float av = a[lane + i*32];
#pragma unroll
            for (int t = 0; t < 8; t++) acc[t] += xs[t][lane + i*32] * av;
        }
#pragma unroll
        for (int off = 16; off; off >>= 1) {
#pragma unroll
            for (int t = 0; t < 8; t++)
                acc[t] += __shfl_xor_sync(0xffffffffu, acc[t], off);
        }
        if (lane == 0) {
#pragma unroll
            for (int t = 0; t < 8; t++)
                g_h[(size_t)(tok0 + t)*48 + j] = tanhf(acc[t]);
        }
    }
}

// ---------------- kernel 2: mod inputs -> fp16 (R11 body; d split over gridDim.y) ------
__global__ void __launch_bounds__(256) mod_input3_kernel(const float* __restrict__ x,
                                                         const float* __restrict__ qb, const float* __restrict__ ql,
                                                         const float* __restrict__ kb, const float* __restrict__ kl,
                                                         const float* __restrict__ vb, const float* __restrict__ vl) {
    const int tok0 = blockIdx.x * 32;
    const int d0   = blockIdx.y * 512;
    __shared__ float hs[32][48];
    const int tid = threadIdx.x;
    for (int i = tid; i < 32*48; i += 256) {
        int t = i / 48, j = i % 48;
        hs[t][j] = g_h[(size_t)(tok0 + t)*48 + j];
    }
    __syncthreads();

#pragma unroll
    for (int c = 0; c < 2; c++) {
        const int d = d0 + tid + c*256;
        float bq[LORA_D], bk[LORA_D], bv[LORA_D];
        const float4* qrow = (const float4*)(qb + (size_t)d * LORA_D);
        const float4* krow = (const float4*)(kb + (size_t)d * LORA_D);
        const float4* vrow = (const float4*)(vb + (size_t)d * LORA_D);
#pragma unroll
        for (int q4 = 0; q4 < 4; q4++) {
            float4 w;
            w = qrow[q4]; bq[q4*4+0]=w.x; bq[q4*4+1]=w.y; bq[q4*4+2]=w.z; bq[q4*4+3]=w.w;
            w = krow[q4]; bk[q4*4+0]=w.x; bk[q4*4+1]=w.y; bk[q4*4+2]=w.z; bk[q4*4+3]=w.w;
            w = vrow[q4]; bv[q4*4+0]=w.x; bv[q4*4+1]=w.y; bv[q4*4+2]=w.z; bv[q4*4+3]=w.w;
        }
        const float lq = ql[d], lk = kl[d], lv = vl[d];
        float xprev = ((tok0 % TT) == 0) ? 0.f : x[(size_t)(tok0 - 1)*DIMN + d];
        for (int t = 0; t < 32; t++) {
            float xv = x[(size_t)(tok0 + t)*DIMN + d];
            float rq = lq, rk = lk, rv = lv;
#pragma unroll
            for (int j = 0; j < LORA_D; j++) {
                rq += hs[t][j]      * bq[j];
                rk += hs[t][16 + j] * bk[j];
                rv += hs[t][32 + j] * bv[j];
            }
            const float dx = xprev - xv;
            const size_t o = (size_t)(tok0 + t)*DIMN + d;
            g_qcat[o] = __float2half_rn(xv + dx*rq);
            g_kcat[o] = __float2half_rn(xv + dx*rk);
            g_vcat[o] = __float2half_rn(xv + dx*rv);
            xprev = xv;
        }
    }
}

// ---------------- kernel 2c: all 4 weights -> fp16 ----------------
__global__ void __launch_bounds__(256) split_w4_kernel(const float* __restrict__ qw,
                                                       const float* __restrict__ kw,
                                                       const float* __restrict__ vw,
                                                       const float* __restrict__ pw) {
    const int which = blockIdx.y;
    const float* in = (which == 0) ? qw : (which == 1) ? kw : (which == 2) ? vw : pw;
    __half* out = (which == 0) ? g_wq : (which == 1) ? g_wk : (which == 2) ? g_wv : g_wp;
    const int idx = blockIdx.x * 256 + threadIdx.x;
    out[idx] = __float2half_rn(in[idx]);
}

// ---------------- GEMM body: 256x128 tile, 3-stage ----------------
// MODE 0: fp32 C store (+bias).  MODE 1: fused RoPE/cvt fp16 store to OH in [bh][t][64]
#define GSTAGE 49152
#define GSMEM  (3*GSTAGE)

template<int KACT, int NIT, int MODE>
__device__ __forceinline__ void gemm_body(const __half* __restrict__ A,
                                          const __half* __restrict__ W,
                                          const float* __restrict__ bias,
                                          float* __restrict__ C,
                                          __half* __restrict__ OH,
                                          int do_rope,
                                          char* smem, int bx, int by) {
    const unsigned int su = (unsigned int)__cvta_generic_to_shared(smem);
    const int tid  = threadIdx.x;
    const int lane = tid & 31, warp = tid >> 5;
    const int wm = warp >> 1, wn = warp & 1;
    const int m0 = by * 256, n0 = bx * 128;

    float acc[4][8][4];
#pragma unroll
    for (int i = 0; i < 4; i++)
#pragma unroll
        for (int j = 0; j < 8; j++)
#pragma unroll
            for (int e = 0; e < 4; e++) acc[i][j][e] = 0.f;

    const int crow = tid >> 3;
    const int cc   = tid & 7;

    auto issue = [&](int s) {
        const int k0 = s * 64;
        const int kw = k0 & 1023;
        const unsigned int base = su + (unsigned int)((s % 3) * GSTAGE);
#pragma unroll
        for (int e = 0; e < 8; e++) {
            const int row = crow + e * 32;
            const unsigned int sw = (unsigned int)((cc ^ (row & 7)) << 4);
            cpa16(base + row*128 + sw, A + (size_t)(m0 + row)*KACT + k0 + cc*8);
        }
#pragma unroll
        for (int e = 0; e < 4; e++) {
            const int row = crow + e * 32;
            const unsigned int sw = (unsigned int)((cc ^ (row & 7)) << 4);
            cpa16(base + 32768 + row*128 + sw, W + (size_t)(n0 + row)*DIMN + kw + cc*8);
        }
        asm volatile("cp.async.commit_group;\n");
    };

    issue(0);
    issue(1);

    const int krow = lane & 15;
    const int hi16 = lane >> 4;

    for (int it = 0; it < NIT; it++) {
        if (it < NIT-1) asm volatile("cp.async.wait_group 1;\n");
        else            asm volatile("cp.async.wait_group 0;\n");
        __syncthreads();
        if (it + 2 < NIT) issue(it + 2);

        const unsigned int Ab = su + (unsigned int)((it % 3) * GSTAGE);
        const unsigned int Wb = Ab + 32768;

#pragma unroll
        for (int ks = 0; ks < 4; ks++) {
            unsigned int a[4][4], b[4][4];
#pragma unroll
            for (int im = 0; im < 4; im++) {
                const int row = wm*64 + im*16 + krow;
                ldsm4(Ab + (unsigned int)(row*128 + (((2*ks + hi16) ^ (row & 7)) << 4)), a[im]);
            }
#pragma unroll
            for (int jn = 0; jn < 4; jn++) {
                const int row = wn*64 + jn*16 + krow;
                ldsm4(Wb + (unsigned int)(row*128 + (((2*ks + hi16) ^ (row & 7)) << 4)), b[jn]);
            }
#pragma unroll
            for (int im = 0; im < 4; im++)
#pragma unroll
                for (int j8 = 0; j8 < 8; j8++) {
                    const int jn = j8 >> 1, p = j8 & 1;
                    mmah(acc[im][j8], a[im][0], a[im][1], a[im][2], a[im][3],
                         b[jn][p], b[jn][2 + p]);
                }
        }
    }

    if (MODE == 0) {
#pragma unroll
        for (int im = 0; im < 4; im++) {
            const int r0 = m0 + wm*64 + im*16 + (lane >> 2);
#pragma unroll
            for (int j8 = 0; j8 < 8; j8++) {
                const int col = n0 + wn*64 + j8*8 + 2*(lane & 3);
                float b0 = 0.f, b1 = 0.f;
                if (bias) { b0 = bias[col]; b1 = bias[col + 1]; }
                *(float2*)&C[(size_t)r0*1024 + col]       = make_float2(acc[im][j8][0] + b0, acc[im][j8][1] + b1);
                *(float2*)&C[(size_t)(r0 + 8)*1024 + col] = make_float2(acc[im][j8][2] + b0, acc[im][j8][3] + b1);
            }
        }
    } else {
        const int head = bx*2 + wn;                     // 2 heads per N-tile
#pragma unroll
        for (int im = 0; im < 4; im++) {
            const int r0 = m0 + wm*64 + im*16 + (lane >> 2);
            const int b = r0 >> 10, t0 = r0 & 1023, t1 = t0 + 8;
            const size_t d0 = ((size_t)(b*16 + head)*TT + t0)*HDIM;
            const size_t d1 = d0 + 8*HDIM;
            if (do_rope) {
#pragma unroll
                for (int j8 = 0; j8 < 4; j8++) {
                    const int hd = j8*8 + 2*(lane & 3);
                    const float2 ca0 = g_rope[t0*32 + hd];
                    const float2 cb0 = g_rope[t0*32 + hd + 1];
                    const float2 ca1 = g_rope[t1*32 + hd];
                    const float2 cb1 = g_rope[t1*32 + hd + 1];
                    const float xr0 = acc[im][j8][0],   xi0 = acc[im][j8+4][0];
                    const float xr1 = acc[im][j8][1],   xi1 = acc[im][j8+4][1];
                    const float xr2 = acc[im][j8][2],   xi2 = acc[im][j8+4][2];
                    const float xr3 = acc[im][j8][3],   xi3 = acc[im][j8+4][3];
                    *(__half2*)&OH[d0 + hd] = __halves2half2(
                        __float2half_rn(xr0*ca0.x - xi0*ca0.y),
                        __float2half_rn(xr1*cb0.x - xi1*cb0.y));
                    *(__half2*)&OH[d0 + hd + 32] = __halves2half2(
                        __float2half_rn(xr0*ca0.y + xi0*ca0.x),
                        __float2half_rn(xr1*cb0.y + xi1*cb0.x));
                    *(__half2*)&OH[d1 + hd] = __halves2half2(
                        __float2half_rn(xr2*ca1.x - xi2*ca1.y),
                        __float2half_rn(xr3*cb1.x - xi3*cb1.y));
                    *(__half2*)&OH[d1 + hd + 32] = __halves2half2(
                        __float2half_rn(xr2*ca1.y + xi2*ca1.x),
                        __float2half_rn(xr3*cb1.y + xi3*cb1.x));
                }
            } else {
#pragma unroll
                for (int j8 = 0; j8 < 8; j8++) {
                    const int hd = j8*8 + 2*(lane & 3);
                    *(__half2*)&OH[d0 + hd] = __halves2half2(
                        __float2half_rn(acc[im][j8][0]), __float2half_rn(acc[im][j8][1]));
                    *(__half2*)&OH[d1 + hd] = __halves2half2(
                        __float2half_rn(acc[im][j8][2]), __float2half_rn(acc[im][j8][3]));
                }
            }
        }
    }
}

// batched q/k/v GEMM (single-term, K=1024) with fused RoPE/cvt epilogue
__global__ void __launch_bounds__(256, 1) gemm_qkv_kernel() {
    extern __shared__ char smem[];
    const int z = blockIdx.z;
    const __half* A = (z == 0) ? g_qcat : (z == 1) ? g_kcat : g_vcat;
    const __half* W = (z == 0) ? g_wq   : (z == 1) ? g_wk   : g_wv;
    __half*      O = (z == 0) ? g_qh   : (z == 1) ? g_kh   : g_vh;
    gemm_body<DIMN, 16, 1>(A, W, nullptr, nullptr, O, (z < 2) ? 1 : 0,
                           smem, blockIdx.x, blockIdx.y);
}

// proj GEMM (2-term, K=2048)
__global__ void __launch_bounds__(256, 1) gemm_proj_kernel(const float* __restrict__ bias,
                                                           float* __restrict__ out) {
    extern __shared__ char smem[];
    gemm_body<KCATP, 32, 0>(g_acat, g_wp, bias, out, nullptr, 0,
                            smem, blockIdx.x, blockIdx.y);
}

// ---------------- kernel 5: tensor-core causal flash attention (1-seg QK, 1-term PV) --------
#define ATTN_SMEM 40960

__global__ void __launch_bounds__(128, 3) attn_mma_kernel() {
    extern __shared__ char smx[];
    const unsigned int su = (unsigned int)__cvta_generic_to_shared(smx);
    const int tid = threadIdx.x, lane = tid & 31, warp = tid >> 5;
    const int bx = blockIdx.x;
    const int qt = 15 - (bx >> 6);
    const int bh = bx & 63;
    const int q0 = qt * 64;
    const int nk = qt + 1;
    const size_t hb = (size_t)bh * (TT * HDIM);

    auto ldt = [&](unsigned int dstBase, const __half* g, int row0) {
#pragma unroll
        for (int e2 = 0; e2 < 4; e2++) {
            int idx = tid + e2*128;
            int r = idx >> 3, ch = idx & 7;
            cpa16(dstBase + (unsigned int)(r*128 + ((ch ^ (r & 7)) << 4)),
                  g + hb + (size_t)(row0 + r)*HDIM + ch*8);
        }
    };
    auto issue_kv = [&](int kt) {
        unsigned int base = su + 8192u + (unsigned int)((kt & 1) * 16384);
        ldt(base,         g_kh, kt*64);
        ldt(base + 8192u, g_vh, kt*64);
        asm volatile("cp.async.commit_group;\n");
    };

    ldt(su, g_qh, q0);
    asm volatile("cp.async.commit_group;\n");
    issue_kv(0);
    if (nk > 1) { issue_kv(1); asm volatile("cp.async.wait_group 1;\n"); }
    else        {              asm volatile("cp.async.wait_group 0;\n"); }
    __syncthreads();

    const int hi16 = lane >> 4;
    const int krow = lane & 15;
    const int wrow = warp*16 + (lane >> 2);

    unsigned int aq[4][4];
    {
        const int qrow = warp*16 + krow;
#pragma unroll
        for (int ck = 0; ck < 4; ck++)
            ldsm4(su + (unsigned int)(qrow*128 + (((2*ck + hi16) ^ (qrow & 7)) << 4)), aq[ck]);
    }

    float oacc[8][4], lacc[4];
#pragma unroll
    for (int j = 0; j < 8; j++)
#pragma unroll
        for (int e = 0; e < 4; e++) oacc[j][e] = 0.f;
#pragma unroll
    for (int e = 0; e < 4; e++) lacc[e] = 0.f;
    float m0 = -1e30f, m1 = -1e30f;

    const unsigned int ONES = 0x3C003C00u;

    for (int kt = 0; kt < nk; kt++) {
        const unsigned int sb = su + 8192u + (unsigned int)((kt & 1) * 16384);

        float c[8][4];
#pragma unroll
        for (int j = 0; j < 8; j++)
#pragma unroll
            for (int e = 0; e < 4; e++) c[j][e] = 0.f;

        // ---- S = Qh · Kh^T ----
#pragma unroll
        for (int ck = 0; ck < 4; ck++) {
#pragma unroll
            for (int g = 0; g < 4; g++) {
                unsigned int bq[4];
                const int row = g*16 + krow;
                ldsm4(sb + (unsigned int)(row*128 + (((2*ck + hi16) ^ (row & 7)) << 4)), bq);
                mmah(c[2*g],   aq[ck][0], aq[ck][1], aq[ck][2], aq[ck][3], bq[0], bq[2]);
                mmah(c[2*g+1], aq[ck][0], aq[ck][1], aq[ck][2], aq[ck][3], bq[1], bq[3]);
            }
        }

        const float alpha = 0.18033688011112042f;   // 0.125 * log2(e)
#pragma unroll
        for (int j = 0; j < 8; j++) {
            c[j][0] *= alpha; c[j][1] *= alpha; c[j][2] *= alpha; c[j][3] *= alpha;
        }
        if (kt == qt) {
#pragma unroll
            for (int j = 0; j < 8; j++) {
                const int cb = 8*j + 2*(lane & 3);
                if (cb     > wrow)     c[j][0] = -30000.f;
                if (cb + 1 > wrow)     c[j][1] = -30000.f;
                if (cb     > wrow + 8) c[j][2] = -30000.f;
                if (cb + 1 > wrow + 8) c[j][3] = -30000.f;
            }
        }
        float ml0 = -1e30f, ml1 = -1e30f;
#pragma unroll
        for (int j = 0; j < 8; j++) {
            ml0 = fmaxf(ml0, fmaxf(c[j][0], c[j][1]));
            ml1 = fmaxf(ml1, fmaxf(c[j][2], c[j][3]));
        }
#pragma unroll
        for (int off = 1; off <= 2; off <<= 1) {
            ml0 = fmaxf(ml0, __shfl_xor_sync(0xffffffffu, ml0, off));
            ml1 = fmaxf(ml1, __shfl_xor_sync(0xffffffffu, ml1, off));
        }
        const float mn0 = fmaxf(m0, ml0), mn1 = fmaxf(m1, ml1);
        const float cr0 = exp2f(m0 - mn0), cr1 = exp2f(m1 - mn1);
        m0 = mn0; m1 = mn1;

        unsigned int pf[2][8];
#pragma unroll
        for (int j = 0; j < 8; j++) {
            pf[0][j] = ex2h2(cvt2h(c[j][1] - m0, c[j][0] - m0));
            pf[1][j] = ex2h2(cvt2h(c[j][3] - m1, c[j][2] - m1));
        }
#pragma unroll
        for (int j = 0; j < 8; j++) {
            oacc[j][0] *= cr0; oacc[j][1] *= cr0;
            oacc[j][2] *= cr1; oacc[j][3] *= cr1;
        }
        lacc[0] *= cr0; lacc[1] *= cr0; lacc[2] *= cr1; lacc[3] *= cr1;

        // ---- O += P Vh, l += P @ ones ----
        const unsigned int Vb = sb + 8192u;
#pragma unroll
        for (int kc = 0; kc < 4; kc++) {
            const unsigned int a0 = pf[0][2*kc],   a1 = pf[1][2*kc];
            const unsigned int a2 = pf[0][2*kc+1], a3 = pf[1][2*kc+1];
            mmah(lacc, a0, a1, a2, a3, ONES, ONES);
            const int rbase = kc*16 + krow;
#pragma unroll
            for (int jj = 0; jj < 4; jj++) {
                unsigned int bv[4];
                ldsm4t(Vb + (unsigned int)(rbase*128 + (((2*jj + hi16) ^ (rbase & 7)) << 4)), bv);
                mmah(oacc[2*jj],   a0, a1, a2, a3, bv[0], bv[1]);
                mmah(oacc[2*jj+1], a0, a1, a2, a3, bv[2], bv[3]);
            }
        }

        if (kt + 1 < nk) {
            __syncthreads();
            if (kt + 2 < nk) {
                issue_kv(kt + 2);
                asm volatile("cp.async.wait_group 1;\n");
            } else {
                asm volatile("cp.async.wait_group 0;\n");
            }
            __syncthreads();
        }
    }

    // ---- epilogue: write fp16 [hi|lo] into g_acat ([tok][2048]) ----
    const float inv0 = 1.f / lacc[0];
    const float inv1 = 1.f / lacc[2];
    const int b = bh >> 4, h = bh & 15;
    const size_t tok0 = (size_t)b*TT + q0 + wrow;
#pragma unroll
    for (int j = 0; j < 8; j++) {
        const int col = 8*j + 2*(lane & 3);
        float a0 = oacc[j][0]*inv0, a1 = oacc[j][1]*inv0;
        float a2 = oacc[j][2]*inv1, a3 = oacc[j][3]*inv1;
        __half h0 = __float2half_rn(a0), h1 = __float2half_rn(a1);
        __half h2 = __float2half_rn(a2), h3 = __float2half_rn(a3);
        __half l0 = __float2half_rn(a0 - __half2float(h0));
        __half l1 = __float2half_rn(a1 - __half2float(h1));
        __half l2 = __float2half_rn(a2 - __half2float(h2));
        __half l3 = __float2half_rn(a3 - __half2float(h3));
        size_t base0 = tok0*KCATP + h*HDIM + col;
        size_t base1 = (tok0 + 8)*KCATP + h*HDIM + col;
        *(__half2*)&g_acat[base0]        = __halves2half2(h0, h1);
        *(__half2*)&g_acat[base0 + 1024] = __halves2half2(l0, l1);
        *(__half2*)&g_acat[base1]        = __halves2half2(h2, h3);
        *(__half2*)&g_acat[base1 + 1024] = __halves2half2(l2, l3);
    }
}

// ---------------- launch ----------------
extern "C" void kernel_launch(void* const* d_in, const int* in_sizes, int n_in,
                              void* d_out, int out_size) {
    const float* x      = (const float*)d_in[0];
    const float* q_w    = (const float*)d_in[1];
    const float* k_w    = (const float*)d_in[2];
    const float* v_w    = (const float*)d_in[3];
    const float* q_a    = (const float*)d_in[4];
    const float* q_b    = (const float*)d_in[5];
    const float* q_l    = (const float*)d_in[6];
    const float* k_a    = (const float*)d_in[7];
    const float* k_b    = (const float*)d_in[8];
    const float* k_l    = (const float*)d_in[9];
    const float* v_a    = (const float*)d_in[10];
    const float* v_b    = (const float*)d_in[11];
    const float* v_l    = (const float*)d_in[12];
    const float* proj_w = (const float*)d_in[13];
    const float* proj_b = (const float*)d_in[14];
    float* out = (float*)d_out;

    cudaFuncSetAttribute(gemm_qkv_kernel,
                         cudaFuncAttributeMaxDynamicSharedMemorySize, GSMEM);
    cudaFuncSetAttribute(gemm_proj_kernel,
                         cudaFuncAttributeMaxDynamicSharedMemorySize, GSMEM);
    cudaFuncSetAttribute(attn_mma_kernel,
                         cudaFuncAttributeMaxDynamicSharedMemorySize, ATTN_SMEM);

    rope_tab_kernel<<<(TT*32)/256, 256>>>();
    split_w4_kernel<<<dim3((DIMN*DIMN)/256, 4), 256>>>(q_w, k_w, v_w, proj_w);
    lora_h_kernel<<<MTOK/8, 256>>>(x, q_a, k_a, v_a);
    mod_input3_kernel<<<dim3(MTOK/32, 2), 256>>>(x, q_b, q_l, k_b, k_l, v_b, v_l);

    gemm_qkv_kernel<<<dim3(8, 16, 3), 256, GSMEM>>>();

    attn_mma_kernel<<<1024, 128, ATTN_SMEM>>>();

    gemm_proj_kernel<<<dim3(8, 16), 256, GSMEM>>>(proj_b, out);
}

// round 15
// speedup vs baseline: 2.5151x; 1.0789x over previous
#include <cuda_runtime.h>
#include <cuda_bf16.h>
#include <cuda_fp16.h>
#include <cstdint>
#include <stdint.h>
#include <math.h>

#define DIMN   1024
#define NHEADS 16
#define HDIM   64
#define LORA_D 16
#define BB     4
#define TT     1024
#define MTOK   (BB*TT)   // 4096

// ---------------- scratch ----------------
__device__ float g_h[MTOK*48];
__device__ __half g_qcat[(size_t)MTOK*DIMN];   // qkv acts: single fp16 term
__device__ __half g_kcat[(size_t)MTOK*DIMN];
__device__ __half g_vcat[(size_t)MTOK*DIMN];
__device__ __half g_acat[(size_t)MTOK*DIMN];   // proj input (fp16, single term)
__device__ __half g_wq[(size_t)DIMN*DIMN];
__device__ __half g_wk[(size_t)DIMN*DIMN];
__device__ __half g_wv[(size_t)DIMN*DIMN];
__device__ __half g_wp[(size_t)DIMN*DIMN];
__device__ __half g_qh[(size_t)MTOK*DIMN];     // [bh][t][64]
__device__ __half g_kh[(size_t)MTOK*DIMN];
__device__ __half g_vh[(size_t)MTOK*DIMN];
__device__ float2 g_rope[TT*32];               // (cos, sin) per (t, j)

// ---------------- asm helpers ----------------
__device__ __forceinline__ void cpa16(unsigned int d, const void* s) {
    asm volatile("cp.async.cg.shared.global [%0], [%1], 16;\n" :: "r"(d), "l"(s));
}
__device__ __forceinline__ void ldsm4(unsigned int a, unsigned int* r) {
    asm volatile("ldmatrix.sync.aligned.m8n8.x4.shared.b16 {%0,%1,%2,%3}, [%4];\n"
        : "=r"(r[0]), "=r"(r[1]), "=r"(r[2]), "=r"(r[3]) : "r"(a));
}
__device__ __forceinline__ void ldsm4t(unsigned int a, unsigned int* r) {
    asm volatile("ldmatrix.sync.aligned.m8n8.x4.trans.shared.b16 {%0,%1,%2,%3}, [%4];\n"
        : "=r"(r[0]), "=r"(r[1]), "=r"(r[2]), "=r"(r[3]) : "r"(a));
}
__device__ __forceinline__ void mmah(float* c, unsigned int a0, unsigned int a1,
                                     unsigned int a2, unsigned int a3,
                                     unsigned int b0, unsigned int b1) {
    asm volatile("mma.sync.aligned.m16n8k16.row.col.f32.f16.f16.f32 "
        "{%0,%1,%2,%3},{%4,%5,%6,%7},{%8,%9},{%0,%1,%2,%3};\n"
        : "+f"(c[0]), "+f"(c[1]), "+f"(c[2]), "+f"(c[3])
        : "r"(a0), "r"(a1), "r"(a2), "r"(a3), "r"(b0), "r"(b1));
}
__device__ __forceinline__ unsigned int ex2h2(unsigned int x) {
    unsigned int d;
    asm("ex2.approx.f16x2 %0, %1;" : "=r"(d) : "r"(x));
    return d;
}
__device__ __forceinline__ unsigned int cvt2h(float hi, float lo) {
    unsigned int d;
    asm("cvt.rn.f16x2.f32 %0, %1, %2;" : "=r"(d) : "f"(hi), "f"(lo));
    return d;
}

// ---------------- kernel 0: rope table ----------------
__global__ void __launch_bounds__(256) rope_tab_kernel() {
    const int idx = blockIdx.x * 256 + threadIdx.x;     // 32768
    const int t = idx >> 5, j = idx & 31;
    float theta = 1.0f / powf(10000.0f, (float)j * (1.0f / 32.0f));
    float ang = (float)t * theta;
    float sn, cs;
    sincosf(ang, &sn, &cs);
    g_rope[idx] = make_float2(cs, sn);
}

// ---------------- kernel 1: H = tanh(x @ Acat^T) ----------
__global__ void __launch_bounds__(256) lora_h_kernel(const float* __restrict__ x,
                                                     const float* __restrict__ qa,
                                                     const float* __restrict__ ka,
                                                     const float* __restrict__ va) {
    __shared__ float xs[8][DIMN];
    const int tok0 = blockIdx.x * 8;
    const int tid  = threadIdx.x;

    const float4* xg  = (const float4*)(x + (size_t)tok0 * DIMN);
    float4*       xs4 = (float4*)&xs[0][0];
#pragma unroll
    for (int i = 0; i < 8; i++) xs4[tid + i*256] = xg[tid + i*256];
    __syncthreads();

    const int warp = tid >> 5, lane = tid & 31;
#pragma unroll
    for (int jj = 0; jj < 6; jj++) {
        const int j = warp * 6 + jj;
        const float* a = (j < 16) ? (qa + j*DIMN)
                       : (j < 32) ? (ka + (j-16)*DIMN)
                                  : (va + (j-32)*DIMN);
        float acc[8];
#pragma unroll
        for (int t = 0; t < 8; t++) acc[t] = 0.f;
        for (int i = 0; i < 32; i++) {
            float av = a[lane + i*32];
#pragma unroll
            for (int t = 0; t < 8; t++) acc[t] += xs[t][lane + i*32] * av;
        }
#pragma unroll
        for (int off = 16; off; off >>= 1) {
#pragma unroll
            for (int t = 0; t < 8; t++)
                acc[t] += __shfl_xor_sync(0xffffffffu, acc[t], off);
        }
        if (lane == 0) {
#pragma unroll
            for (int t = 0; t < 8; t++)
                g_h[(size_t)(tok0 + t)*48 + j] = tanhf(acc[t]);
        }
    }
}

// ---------------- kernel 2: mod inputs -> fp16 (R14 body; d split over gridDim.y=4) ------
__global__ void __launch_bounds__(256) mod_input3_kernel(const float* __restrict__ x,
                                                         const float* __restrict__ qb, const float* __restrict__ ql,
                                                         const float* __restrict__ kb, const float* __restrict__ kl,
                                                         const float* __restrict__ vb, const float* __restrict__ vl) {
    const int tok0 = blockIdx.x * 32;
    __shared__ float hs[32][48];
    const int tid = threadIdx.x;
    for (int i = tid; i < 32*48; i += 256) {
        int t = i / 48, j = i % 48;
        hs[t][j] = g_h[(size_t)(tok0 + t)*48 + j];
    }
    __syncthreads();

    {
        const int d = blockIdx.y * 256 + tid;
        float bq[LORA_D], bk[LORA_D], bv[LORA_D];
        const float4* qrow = (const float4*)(qb + (size_t)d * LORA_D);
        const float4* krow = (const float4*)(kb + (size_t)d * LORA_D);
        const float4* vrow = (const float4*)(vb + (size_t)d * LORA_D);
#pragma unroll
        for (int q4 = 0; q4 < 4; q4++) {
            float4 w;
            w = qrow[q4]; bq[q4*4+0]=w.x; bq[q4*4+1]=w.y; bq[q4*4+2]=w.z; bq[q4*4+3]=w.w;
            w = krow[q4]; bk[q4*4+0]=w.x; bk[q4*4+1]=w.y; bk[q4*4+2]=w.z; bk[q4*4+3]=w.w;
            w = vrow[q4]; bv[q4*4+0]=w.x; bv[q4*4+1]=w.y; bv[q4*4+2]=w.z; bv[q4*4+3]=w.w;
        }
        const float lq = ql[d], lk = kl[d], lv = vl[d];
        float xprev = ((tok0 % TT) == 0) ? 0.f : x[(size_t)(tok0 - 1)*DIMN + d];
        for (int t = 0; t < 32; t++) {
            float xv = x[(size_t)(tok0 + t)*DIMN + d];
            float rq = lq, rk = lk, rv = lv;
#pragma unroll
            for (int j = 0; j < LORA_D; j++) {
                rq += hs[t][j]      * bq[j];
                rk += hs[t][16 + j] * bk[j];
                rv += hs[t][32 + j] * bv[j];
            }
            const float dx = xprev - xv;
            const size_t o = (size_t)(tok0 + t)*DIMN + d;
            g_qcat[o] = __float2half_rn(xv + dx*rq);
            g_kcat[o] = __float2half_rn(xv + dx*rk);
            g_vcat[o] = __float2half_rn(xv + dx*rv);
            xprev = xv;
        }
    }
}

// ---------------- kernel 2c: all 4 weights -> fp16 ----------------
__global__ void __launch_bounds__(256) split_w4_kernel(const float* __restrict__ qw,
                                                       const float* __restrict__ kw,
                                                       const float* __restrict__ vw,
                                                       const float* __restrict__ pw) {
    const int which = blockIdx.y;
    const float* in = (which == 0) ? qw : (which == 1) ? kw : (which == 2) ? vw : pw;
    __half* out = (which == 0) ? g_wq : (which == 1) ? g_wk : (which == 2) ? g_wv : g_wp;
    const int idx = blockIdx.x * 256 + threadIdx.x;
    out[idx] = __float2half_rn(in[idx]);
}

// ---------------- GEMM body: 256x128 tile, 3-stage ----------------
// MODE 0: fp32 C store (+bias).  MODE 1: fused RoPE/cvt fp16 store to OH in [bh][t][64]
#define GSTAGE 49152
#define GSMEM  (3*GSTAGE)

template<int KACT, int NIT, int MODE>
__device__ __forceinline__ void gemm_body(const __half* __restrict__ A,
                                          const __half* __restrict__ W,
                                          const float* __restrict__ bias,
                                          float* __restrict__ C,
                                          __half* __restrict__ OH,
                                          int do_rope,
                                          char* smem, int bx, int by) {
    const unsigned int su = (unsigned int)__cvta_generic_to_shared(smem);
    const int tid  = threadIdx.x;
    const int lane = tid & 31, warp = tid >> 5;
    const int wm = warp >> 1, wn = warp & 1;
    const int m0 = by * 256, n0 = bx * 128;

    float acc[4][8][4];
#pragma unroll
    for (int i = 0; i < 4; i++)
#pragma unroll
        for (int j = 0; j < 8; j++)
#pragma unroll
            for (int e = 0; e < 4; e++) acc[i][j][e] = 0.f;

    const int crow = tid >> 3;
    const int cc   = tid & 7;

    auto issue = [&](int s) {
        const int k0 = s * 64;
        const int kw = k0 & 1023;
        const unsigned int base = su + (unsigned int)((s % 3) * GSTAGE);
#pragma unroll
        for (int e = 0; e < 8; e++) {
            const int row = crow + e * 32;
            const unsigned int sw = (unsigned int)((cc ^ (row & 7)) << 4);
            cpa16(base + row*128 + sw, A + (size_t)(m0 + row)*KACT + k0 + cc*8);
        }
#pragma unroll
        for (int e = 0; e < 4; e++) {
            const int row = crow + e * 32;
            const unsigned int sw = (unsigned int)((cc ^ (row & 7)) << 4);
            cpa16(base + 32768 + row*128 + sw, W + (size_t)(n0 + row)*DIMN + kw + cc*8);
        }
        asm volatile("cp.async.commit_group;\n");
    };

    issue(0);
    issue(1);

    const int krow = lane & 15;
    const int hi16 = lane >> 4;

    for (int it = 0; it < NIT; it++) {
        if (it < NIT-1) asm volatile("cp.async.wait_group 1;\n");
        else            asm volatile("cp.async.wait_group 0;\n");
        __syncthreads();
        if (it + 2 < NIT) issue(it + 2);

        const unsigned int Ab = su + (unsigned int)((it % 3) * GSTAGE);
        const unsigned int Wb = Ab + 32768;

#pragma unroll
        for (int ks = 0; ks < 4; ks++) {
            unsigned int a[4][4], b[4][4];
#pragma unroll
            for (int im = 0; im < 4; im++) {
                const int row = wm*64 + im*16 + krow;
                ldsm4(Ab + (unsigned int)(row*128 + (((2*ks + hi16) ^ (row & 7)) << 4)), a[im]);
            }
#pragma unroll
            for (int jn = 0; jn < 4; jn++) {
                const int row = wn*64 + jn*16 + krow;
                ldsm4(Wb + (unsigned int)(row*128 + (((2*ks + hi16) ^ (row & 7)) << 4)), b[jn]);
            }
#pragma unroll
            for (int im = 0; im < 4; im++)
#pragma unroll
                for (int j8 = 0; j8 < 8; j8++) {
                    const int jn = j8 >> 1, p = j8 & 1;
                    mmah(acc[im][j8], a[im][0], a[im][1], a[im][2], a[im][3],
                         b[jn][p], b[jn][2 + p]);
                }
        }
    }

    if (MODE == 0) {
#pragma unroll
        for (int im = 0; im < 4; im++) {
            const int r0 = m0 + wm*64 + im*16 + (lane >> 2);
#pragma unroll
            for (int j8 = 0; j8 < 8; j8++) {
                const int col = n0 + wn*64 + j8*8 + 2*(lane & 3);
                float b0 = 0.f, b1 = 0.f;
                if (bias) { b0 = bias[col]; b1 = bias[col + 1]; }
                *(float2*)&C[(size_t)r0*1024 + col]       = make_float2(acc[im][j8][0] + b0, acc[im][j8][1] + b1);
                *(float2*)&C[(size_t)(r0 + 8)*1024 + col] = make_float2(acc[im][j8][2] + b0, acc[im][j8][3] + b1);
            }
        }
    } else {
        const int head = bx*2 + wn;                     // 2 heads per N-tile
#pragma unroll
        for (int im = 0; im < 4; im++) {
            const int r0 = m0 + wm*64 + im*16 + (lane >> 2);
            const int b = r0 >> 10, t0 = r0 & 1023, t1 = t0 + 8;
            const size_t d0 = ((size_t)(b*16 + head)*TT + t0)*HDIM;
            const size_t d1 = d0 + 8*HDIM;
            if (do_rope) {
#pragma unroll
                for (int j8 = 0; j8 < 4; j8++) {
                    const int hd = j8*8 + 2*(lane & 3);
                    const float2 ca0 = g_rope[t0*32 + hd];
                    const float2 cb0 = g_rope[t0*32 + hd + 1];
                    const float2 ca1 = g_rope[t1*32 + hd];
                    const float2 cb1 = g_rope[t1*32 + hd + 1];
                    const float xr0 = acc[im][j8][0],   xi0 = acc[im][j8+4][0];
                    const float xr1 = acc[im][j8][1],   xi1 = acc[im][j8+4][1];
                    const float xr2 = acc[im][j8][2],   xi2 = acc[im][j8+4][2];
                    const float xr3 = acc[im][j8][3],   xi3 = acc[im][j8+4][3];
                    *(__half2*)&OH[d0 + hd] = __halves2half2(
                        __float2half_rn(xr0*ca0.x - xi0*ca0.y),
                        __float2half_rn(xr1*cb0.x - xi1*cb0.y));
                    *(__half2*)&OH[d0 + hd + 32] = __halves2half2(
                        __float2half_rn(xr0*ca0.y + xi0*ca0.x),
                        __float2half_rn(xr1*cb0.y + xi1*cb0.x));
                    *(__half2*)&OH[d1 + hd] = __halves2half2(
                        __float2half_rn(xr2*ca1.x - xi2*ca1.y),
                        __float2half_rn(xr3*cb1.x - xi3*cb1.y));
                    *(__half2*)&OH[d1 + hd + 32] = __halves2half2(
                        __float2half_rn(xr2*ca1.y + xi2*ca1.x),
                        __float2half_rn(xr3*cb1.y + xi3*cb1.x));
                }
            } else {
#pragma unroll
                for (int j8 = 0; j8 < 8; j8++) {
                    const int hd = j8*8 + 2*(lane & 3);
                    *(__half2*)&OH[d0 + hd] = __halves2half2(
                        __float2half_rn(acc[im][j8][0]), __float2half_rn(acc[im][j8][1]));
                    *(__half2*)&OH[d1 + hd] = __halves2half2(
                        __float2half_rn(acc[im][j8][2]), __float2half_rn(acc[im][j8][3]));
                }
            }
        }
    }
}

// batched q/k/v GEMM (single-term, K=1024) with fused RoPE/cvt epilogue
__global__ void __launch_bounds__(256, 1) gemm_qkv_kernel() {
    extern __shared__ char smem[];
    const int z = blockIdx.z;
    const __half* A = (z == 0) ? g_qcat : (z == 1) ? g_kcat : g_vcat;
    const __half* W = (z == 0) ? g_wq   : (z == 1) ? g_wk   : g_wv;
    __half*      O = (z == 0) ? g_qh   : (z == 1) ? g_kh   : g_vh;
    gemm_body<DIMN, 16, 1>(A, W, nullptr, nullptr, O, (z < 2) ? 1 : 0,
                           smem, blockIdx.x, blockIdx.y);
}

// proj GEMM (single-term, K=1024)
__global__ void __launch_bounds__(256, 1) gemm_proj_kernel(const float* __restrict__ bias,
                                                           float* __restrict__ out) {
    extern __shared__ char smem[];
    gemm_body<DIMN, 16, 0>(g_acat, g_wp, bias, out, nullptr, 0,
                           smem, blockIdx.x, blockIdx.y);
}

// ---------------- kernel 5: tensor-core causal flash attention (1-seg QK, 1-term PV) --------
#define ATTN_SMEM 40960

__global__ void __launch_bounds__(128, 3) attn_mma_kernel() {
    extern __shared__ char smx[];
    const unsigned int su = (unsigned int)__cvta_generic_to_shared(smx);
    const int tid = threadIdx.x, lane = tid & 31, warp = tid >> 5;
    const int bx = blockIdx.x;
    const int qt = 15 - (bx >> 6);
    const int bh = bx & 63;
    const int q0 = qt * 64;
    const int nk = qt + 1;
    const size_t hb = (size_t)bh * (TT * HDIM);

    auto ldt = [&](unsigned int dstBase, const __half* g, int row0) {
#pragma unroll
        for (int e2 = 0; e2 < 4; e2++) {
            int idx = tid + e2*128;
            int r = idx >> 3, ch = idx & 7;
            cpa16(dstBase + (unsigned int)(r*128 + ((ch ^ (r & 7)) << 4)),
                  g + hb + (size_t)(row0 + r)*HDIM + ch*8);
        }
    };
    auto issue_kv = [&](int kt) {
        unsigned int base = su + 8192u + (unsigned int)((kt & 1) * 16384);
        ldt(base,         g_kh, kt*64);
        ldt(base + 8192u, g_vh, kt*64);
        asm volatile("cp.async.commit_group;\n");
    };

    ldt(su, g_qh, q0);
    asm volatile("cp.async.commit_group;\n");
    issue_kv(0);
    if (nk > 1) { issue_kv(1); asm volatile("cp.async.wait_group 1;\n"); }
    else        {              asm volatile("cp.async.wait_group 0;\n"); }
    __syncthreads();

    const int hi16 = lane >> 4;
    const int krow = lane & 15;
    const int wrow = warp*16 + (lane >> 2);

    unsigned int aq[4][4];
    {
        const int qrow = warp*16 + krow;
#pragma unroll
        for (int ck = 0; ck < 4; ck++)
            ldsm4(su + (unsigned int)(qrow*128 + (((2*ck + hi16) ^ (qrow & 7)) << 4)), aq[ck]);
    }

    float oacc[8][4], lacc[4];
#pragma unroll
    for (int j = 0; j < 8; j++)
#pragma unroll
        for (int e = 0; e < 4; e++) oacc[j][e] = 0.f;
#pragma unroll
    for (int e = 0; e < 4; e++) lacc[e] = 0.f;
    float m0 = -1e30f, m1 = -1e30f;

    const unsigned int ONES = 0x3C003C00u;

    for (int kt = 0; kt < nk; kt++) {
        const unsigned int sb = su + 8192u + (unsigned int)((kt & 1) * 16384);

        float c[8][4];
#pragma unroll
        for (int j = 0; j < 8; j++)
#pragma unroll
            for (int e = 0; e < 4; e++) c[j][e] = 0.f;

        // ---- S = Qh · Kh^T ----
#pragma unroll
        for (int ck = 0; ck < 4; ck++) {
#pragma unroll
            for (int g = 0; g < 4; g++) {
                unsigned int bq[4];
                const int row = g*16 + krow;
                ldsm4(sb + (unsigned int)(row*128 + (((2*ck + hi16) ^ (row & 7)) << 4)), bq);
                mmah(c[2*g],   aq[ck][0], aq[ck][1], aq[ck][2], aq[ck][3], bq[0], bq[2]);
                mmah(c[2*g+1], aq[ck][0], aq[ck][1], aq[ck][2], aq[ck][3], bq[1], bq[3]);
            }
        }

        const float alpha = 0.18033688011112042f;   // 0.125 * log2(e)
#pragma unroll
        for (int j = 0; j < 8; j++) {
            c[j][0] *= alpha; c[j][1] *= alpha; c[j][2] *= alpha; c[j][3] *= alpha;
        }
        if (kt == qt) {
#pragma unroll
            for (int j = 0; j < 8; j++) {
                const int cb = 8*j + 2*(lane & 3);
                if (cb     > wrow)     c[j][0] = -30000.f;
                if (cb + 1 > wrow)     c[j][1] = -30000.f;
                if (cb     > wrow + 8) c[j][2] = -30000.f;
                if (cb + 1 > wrow + 8) c[j][3] = -30000.f;
            }
        }
        float ml0 = -1e30f, ml1 = -1e30f;
#pragma unroll
        for (int j = 0; j < 8; j++) {
            ml0 = fmaxf(ml0, fmaxf(c[j][0], c[j][1]));
            ml1 = fmaxf(ml1, fmaxf(c[j][2], c[j][3]));
        }
#pragma unroll
        for (int off = 1; off <= 2; off <<= 1) {
            ml0 = fmaxf(ml0, __shfl_xor_sync(0xffffffffu, ml0, off));
            ml1 = fmaxf(ml1, __shfl_xor_sync(0xffffffffu, ml1, off));
        }
        const float mn0 = fmaxf(m0, ml0), mn1 = fmaxf(m1, ml1);
        const float cr0 = exp2f(m0 - mn0), cr1 = exp2f(m1 - mn1);
        m0 = mn0; m1 = mn1;

        unsigned int pf[2][8];
#pragma unroll
        for (int j = 0; j < 8; j++) {
            pf[0][j] = ex2h2(cvt2h(c[j][1] - m0, c[j][0] - m0));
            pf[1][j] = ex2h2(cvt2h(c[j][3] - m1, c[j][2] - m1));
        }
#pragma unroll
        for (int j = 0; j < 8; j++) {
            oacc[j][0] *= cr0; oacc[j][1] *= cr0;
            oacc[j][2] *= cr1; oacc[j][3] *= cr1;
        }
        lacc[0] *= cr0; lacc[1] *= cr0; lacc[2] *= cr1; lacc[3] *= cr1;

        // ---- O += P Vh, l += P @ ones ----
        const unsigned int Vb = sb + 8192u;
#pragma unroll
        for (int kc = 0; kc < 4; kc++) {
            const unsigned int a0 = pf[0][2*kc],   a1 = pf[1][2*kc];
            const unsigned int a2 = pf[0][2*kc+1], a3 = pf[1][2*kc+1];
            mmah(lacc, a0, a1, a2, a3, ONES, ONES);
            const int rbase = kc*16 + krow;
#pragma unroll
            for (int jj = 0; jj < 4; jj++) {
                unsigned int bv[4];
                ldsm4t(Vb + (unsigned int)(rbase*128 + (((2*jj + hi16) ^ (rbase & 7)) << 4)), bv);
                mmah(oacc[2*jj],   a0, a1, a2, a3, bv[0], bv[1]);
                mmah(oacc[2*jj+1], a0, a1, a2, a3, bv[2], bv[3]);
            }
        }

        if (kt + 1 < nk) {
            __syncthreads();
            if (kt + 2 < nk) {
                issue_kv(kt + 2);
                asm volatile("cp.async.wait_group 1;\n");
            } else {
                asm volatile("cp.async.wait_group 0;\n");
            }
            __syncthreads();
        }
    }

    // ---- epilogue: write fp16 into g_acat ([tok][1024]) ----
    const float inv0 = 1.f / lacc[0];
    const float inv1 = 1.f / lacc[2];
    const int b = bh >> 4, h = bh & 15;
    const size_t tok0 = (size_t)b*TT + q0 + wrow;
#pragma unroll
    for (int j = 0; j < 8; j++) {
        const int col = 8*j + 2*(lane & 3);
        float a0 = oacc[j][0]*inv0, a1 = oacc[j][1]*inv0;
        float a2 = oacc[j][2]*inv1, a3 = oacc[j][3]*inv1;
        size_t base0 = tok0*DIMN + h*HDIM + col;
        size_t base1 = (tok0 + 8)*DIMN + h*HDIM + col;
        *(__half2*)&g_acat[base0] = __halves2half2(__float2half_rn(a0), __float2half_rn(a1));
        *(__half2*)&g_acat[base1] = __halves2half2(__float2half_rn(a2), __float2half_rn(a3));
    }
}

// ---------------- launch ----------------
extern "C" void kernel_launch(void* const* d_in, const int* in_sizes, int n_in,
                              void* d_out, int out_size) {
    const float* x      = (const float*)d_in[0];
    const float* q_w    = (const float*)d_in[1];
    const float* k_w    = (const float*)d_in[2];
    const float* v_w    = (const float*)d_in[3];
    const float* q_a    = (const float*)d_in[4];
    const float* q_b    = (const float*)d_in[5];
    const float* q_l    = (const float*)d_in[6];
    const float* k_a    = (const float*)d_in[7];
    const float* k_b    = (const float*)d_in[8];
    const float* k_l    = (const float*)d_in[9];
    const float* v_a    = (const float*)d_in[10];
    const float* v_b    = (const float*)d_in[11];
    const float* v_l    = (const float*)d_in[12];
    const float* proj_w = (const float*)d_in[13];
    const float* proj_b = (const float*)d_in[14];
    float* out = (float*)d_out;

    cudaFuncSetAttribute(gemm_qkv_kernel,
                         cudaFuncAttributeMaxDynamicSharedMemorySize, GSMEM);
    cudaFuncSetAttribute(gemm_proj_kernel,
                         cudaFuncAttributeMaxDynamicSharedMemorySize, GSMEM);
    cudaFuncSetAttribute(attn_mma_kernel,
                         cudaFuncAttributeMaxDynamicSharedMemorySize, ATTN_SMEM);

    rope_tab_kernel<<<(TT*32)/256, 256>>>();
    split_w4_kernel<<<dim3((DIMN*DIMN)/256, 4), 256>>>(q_w, k_w, v_w, proj_w);
    lora_h_kernel<<<MTOK/8, 256>>>(x, q_a, k_a, v_a);
    mod_input3_kernel<<<dim3(MTOK/32, 4), 256>>>(x, q_b, q_l, k_b, k_l, v_b, v_l);

    gemm_qkv_kernel<<<dim3(8, 16, 3), 256, GSMEM>>>();

    attn_mma_kernel<<<1024, 128, ATTN_SMEM>>>();

    gemm_proj_kernel<<<dim3(8, 16), 256, GSMEM>>>(proj_b, out);
}

// round 16
// speedup vs baseline: 2.6109x; 1.0381x over previous
#include <cuda_runtime.h>
#include <cuda_bf16.h>
#include <cuda_fp16.h>
#include <cstdint>
#include <stdint.h>
#include <math.h>

#define DIMN   1024
#define NHEADS 16
#define HDIM   64
#define LORA_D 16
#define BB     4
#define TT     1024
#define MTOK   (BB*TT)   // 4096

// ---------------- scratch ----------------
__device__ float g_h[MTOK*48];
__device__ __half g_qcat[(size_t)MTOK*DIMN];   // qkv acts: single fp16 term
__device__ __half g_kcat[(size_t)MTOK*DIMN];
__device__ __half g_vcat[(size_t)MTOK*DIMN];
__device__ __half g_acat[(size_t)MTOK*DIMN];   // proj input (fp16, single term)
__device__ __half g_wq[(size_t)DIMN*DIMN];
__device__ __half g_wk[(size_t)DIMN*DIMN];
__device__ __half g_wv[(size_t)DIMN*DIMN];
__device__ __half g_wp[(size_t)DIMN*DIMN];
__device__ __half g_qh[(size_t)MTOK*DIMN];     // [bh][t][64]
__device__ __half g_kh[(size_t)MTOK*DIMN];
__device__ __half g_vh[(size_t)MTOK*DIMN];
__device__ float2 g_rope[TT*32];               // (cos, sin) per (t, j)

// ---------------- asm helpers ----------------
__device__ __forceinline__ void cpa16(unsigned int d, const void* s) {
    asm volatile("cp.async.cg.shared.global [%0], [%1], 16;\n" :: "r"(d), "l"(s));
}
__device__ __forceinline__ void ldsm4(unsigned int a, unsigned int* r) {
    asm volatile("ldmatrix.sync.aligned.m8n8.x4.shared.b16 {%0,%1,%2,%3}, [%4];\n"
        : "=r"(r[0]), "=r"(r[1]), "=r"(r[2]), "=r"(r[3]) : "r"(a));
}
__device__ __forceinline__ void ldsm4t(unsigned int a, unsigned int* r) {
    asm volatile("ldmatrix.sync.aligned.m8n8.x4.trans.shared.b16 {%0,%1,%2,%3}, [%4];\n"
        : "=r"(r[0]), "=r"(r[1]), "=r"(r[2]), "=r"(r[3]) : "r"(a));
}
__device__ __forceinline__ void mmah(float* c, unsigned int a0, unsigned int a1,
                                     unsigned int a2, unsigned int a3,
                                     unsigned int b0, unsigned int b1) {
    asm volatile("mma.sync.aligned.m16n8k16.row.col.f32.f16.f16.f32 "
        "{%0,%1,%2,%3},{%4,%5,%6,%7},{%8,%9},{%0,%1,%2,%3};\n"
        : "+f"(c[0]), "+f"(c[1]), "+f"(c[2]), "+f"(c[3])
        : "r"(a0), "r"(a1), "r"(a2), "r"(a3), "r"(b0), "r"(b1));
}
__device__ __forceinline__ unsigned int ex2h2(unsigned int x) {
    unsigned int d;
    asm("ex2.approx.f16x2 %0, %1;" : "=r"(d) : "r"(x));
    return d;
}
__device__ __forceinline__ unsigned int cvt2h(float hi, float lo) {
    unsigned int d;
    asm("cvt.rn.f16x2.f32 %0, %1, %2;" : "=r"(d) : "f"(hi), "f"(lo));
    return d;
}

// ---------------- kernel 0: rope table ----------------
__global__ void __launch_bounds__(256) rope_tab_kernel() {
    const int idx = blockIdx.x * 256 + threadIdx.x;     // 32768
    const int t = idx >> 5, j = idx & 31;
    float theta = 1.0f / powf(10000.0f, (float)j * (1.0f / 32.0f));
    float ang = (float)t * theta;
    float sn, cs;
    sincosf(ang, &sn, &cs);
    g_rope[idx] = make_float2(cs, sn);
}

// ---------------- kernel 1: H = tanh(x @ Acat^T) ----------
__global__ void __launch_bounds__(256) lora_h_kernel(const float* __restrict__ x,
                                                     const float* __restrict__ qa,
                                                     const float* __restrict__ ka,
                                                     const float* __restrict__ va) {
    __shared__ float xs[8][DIMN];
    const int tok0 = blockIdx.x * 8;
    const int tid  = threadIdx.x;

    const float4* xg  = (const float4*)(x + (size_t)tok0 * DIMN);
    float4*       xs4 = (float4*)&xs[0][0];
#pragma unroll
    for (int i = 0; i < 8; i++) xs4[tid + i*256] = xg[tid + i*256];
    __syncthreads();

    const int warp = tid >> 5, lane = tid & 31;
#pragma unroll
    for (int jj = 0; jj < 6; jj++) {
        const int j = warp * 6 + jj;
        const float* a = (j < 16) ? (qa + j*DIMN)
                       : (j < 32) ? (ka + (j-16)*DIMN)
                                  : (va + (j-32)*DIMN);
        float acc[8];
#pragma unroll
        for (int t = 0; t < 8; t++) acc[t] = 0.f;
        for (int i = 0; i < 32; i++) {
            float av = a[lane + i*32];
#pragma unroll
            for (int t = 0; t < 8; t++) acc[t] += xs[t][lane + i*32] * av;
        }
#pragma unroll
        for (int off = 16; off; off >>= 1) {
#pragma unroll
            for (int t = 0; t < 8; t++)
                acc[t] += __shfl_xor_sync(0xffffffffu, acc[t], off);
        }
        if (lane == 0) {
#pragma unroll
            for (int t = 0; t < 8; t++)
                g_h[(size_t)(tok0 + t)*48 + j] = tanhf(acc[t]);
        }
    }
}

// ---------------- kernel 2: mod inputs -> fp16 (R14 config: 32 tok, d split y=2) ------
__global__ void __launch_bounds__(256) mod_input3_kernel(const float* __restrict__ x,
                                                         const float* __restrict__ qb, const float* __restrict__ ql,
                                                         const float* __restrict__ kb, const float* __restrict__ kl,
                                                         const float* __restrict__ vb, const float* __restrict__ vl) {
    const int tok0 = blockIdx.x * 32;
    const int d0   = blockIdx.y * 512;
    __shared__ float hs[32][48];
    const int tid = threadIdx.x;
    for (int i = tid; i < 32*48; i += 256) {
        int t = i / 48, j = i % 48;
        hs[t][j] = g_h[(size_t)(tok0 + t)*48 + j];
    }
    __syncthreads();

#pragma unroll
    for (int c = 0; c < 2; c++) {
        const int d = d0 + tid + c*256;
        float bq[LORA_D], bk[LORA_D], bv[LORA_D];
        const float4* qrow = (const float4*)(qb + (size_t)d * LORA_D);
        const float4* krow = (const float4*)(kb + (size_t)d * LORA_D);
        const float4* vrow = (const float4*)(vb + (size_t)d * LORA_D);
#pragma unroll
        for (int q4 = 0; q4 < 4; q4++) {
            float4 w;
            w = qrow[q4]; bq[q4*4+0]=w.x; bq[q4*4+1]=w.y; bq[q4*4+2]=w.z; bq[q4*4+3]=w.w;
            w = krow[q4]; bk[q4*4+0]=w.x; bk[q4*4+1]=w.y; bk[q4*4+2]=w.z; bk[q4*4+3]=w.w;
            w = vrow[q4]; bv[q4*4+0]=w.x; bv[q4*4+1]=w.y; bv[q4*4+2]=w.z; bv[q4*4+3]=w.w;
        }
        const float lq = ql[d], lk = kl[d], lv = vl[d];
        float xprev = ((tok0 % TT) == 0) ? 0.f : x[(size_t)(tok0 - 1)*DIMN + d];
        for (int t = 0; t < 32; t++) {
            float xv = x[(size_t)(tok0 + t)*DIMN + d];
            float rq = lq, rk = lk, rv = lv;
#pragma unroll
            for (int j = 0; j < LORA_D; j++) {
                rq += hs[t][j]      * bq[j];
                rk += hs[t][16 + j] * bk[j];
                rv += hs[t][32 + j] * bv[j];
            }
            const float dx = xprev - xv;
            const size_t o = (size_t)(tok0 + t)*DIMN + d;
            g_qcat[o] = __float2half_rn(xv + dx*rq);
            g_kcat[o] = __float2half_rn(xv + dx*rk);
            g_vcat[o] = __float2half_rn(xv + dx*rv);
            xprev = xv;
        }
    }
}

// ---------------- kernel 2c: all 4 weights -> fp16 ----------------
__global__ void __launch_bounds__(256) split_w4_kernel(const float* __restrict__ qw,
                                                       const float* __restrict__ kw,
                                                       const float* __restrict__ vw,
                                                       const float* __restrict__ pw) {
    const int which = blockIdx.y;
    const float* in = (which == 0) ? qw : (which == 1) ? kw : (which == 2) ? vw : pw;
    __half* out = (which == 0) ? g_wq : (which == 1) ? g_wk : (which == 2) ? g_wv : g_wp;
    const int idx = blockIdx.x * 256 + threadIdx.x;
    out[idx] = __float2half_rn(in[idx]);
}

// ---------------- GEMM body: 256x128 tile, 3-stage ----------------
// MODE 0: fp32 C store (+bias).  MODE 1: fused RoPE/cvt fp16 store to OH in [bh][t][64]
#define GSTAGE 49152
#define GSMEM  (3*GSTAGE)

template<int KACT, int NIT, int MODE>
__device__ __forceinline__ void gemm_body(const __half* __restrict__ A,
                                          const __half* __restrict__ W,
                                          const float* __restrict__ bias,
                                          float* __restrict__ C,
                                          __half* __restrict__ OH,
                                          int do_rope,
                                          char* smem, int bx, int by) {
    const unsigned int su = (unsigned int)__cvta_generic_to_shared(smem);
    const int tid  = threadIdx.x;
    const int lane = tid & 31, warp = tid >> 5;
    const int wm = warp >> 1, wn = warp & 1;
    const int m0 = by * 256, n0 = bx * 128;

    float acc[4][8][4];
#pragma unroll
    for (int i = 0; i < 4; i++)
#pragma unroll
        for (int j = 0; j < 8; j++)
#pragma unroll
            for (int e = 0; e < 4; e++) acc[i][j][e] = 0.f;

    const int crow = tid >> 3;
    const int cc   = tid & 7;

    auto issue = [&](int s) {
        const int k0 = s * 64;
        const int kw = k0 & 1023;
        const unsigned int base = su + (unsigned int)((s % 3) * GSTAGE);
#pragma unroll
        for (int e = 0; e < 8; e++) {
            const int row = crow + e * 32;
            const unsigned int sw = (unsigned int)((cc ^ (row & 7)) << 4);
            cpa16(base + row*128 + sw, A + (size_t)(m0 + row)*KACT + k0 + cc*8);
        }
#pragma unroll
        for (int e = 0; e < 4; e++) {
            const int row = crow + e * 32;
            const unsigned int sw = (unsigned int)((cc ^ (row & 7)) << 4);
            cpa16(base + 32768 + row*128 + sw, W + (size_t)(n0 + row)*DIMN + kw + cc*8);
        }
        asm volatile("cp.async.commit_group;\n");
    };

    issue(0);
    issue(1);

    const int krow = lane & 15;
    const int hi16 = lane >> 4;

    for (int it = 0; it < NIT; it++) {
        if (it < NIT-1) asm volatile("cp.async.wait_group 1;\n");
        else            asm volatile("cp.async.wait_group 0;\n");
        __syncthreads();
        if (it + 2 < NIT) issue(it + 2);

        const unsigned int Ab = su + (unsigned int)((it % 3) * GSTAGE);
        const unsigned int Wb = Ab + 32768;

#pragma unroll
        for (int ks = 0; ks < 4; ks++) {
            unsigned int a[4][4], b[4][4];
#pragma unroll
            for (int im = 0; im < 4; im++) {
                const int row = wm*64 + im*16 + krow;
                ldsm4(Ab + (unsigned int)(row*128 + (((2*ks + hi16) ^ (row & 7)) << 4)), a[im]);
            }
#pragma unroll
            for (int jn = 0; jn < 4; jn++) {
                const int row = wn*64 + jn*16 + krow;
                ldsm4(Wb + (unsigned int)(row*128 + (((2*ks + hi16) ^ (row & 7)) << 4)), b[jn]);
            }
#pragma unroll
            for (int im = 0; im < 4; im++)
#pragma unroll
                for (int j8 = 0; j8 < 8; j8++) {
                    const int jn = j8 >> 1, p = j8 & 1;
                    mmah(acc[im][j8], a[im][0], a[im][1], a[im][2], a[im][3],
                         b[jn][p], b[jn][2 + p]);
                }
        }
    }

    if (MODE == 0) {
#pragma unroll
        for (int im = 0; im < 4; im++) {
            const int r0 = m0 + wm*64 + im*16 + (lane >> 2);
#pragma unroll
            for (int j8 = 0; j8 < 8; j8++) {
                const int col = n0 + wn*64 + j8*8 + 2*(lane & 3);
                float b0 = 0.f, b1 = 0.f;
                if (bias) { b0 = bias[col]; b1 = bias[col + 1]; }
                *(float2*)&C[(size_t)r0*1024 + col]       = make_float2(acc[im][j8][0] + b0, acc[im][j8][1] + b1);
                *(float2*)&C[(size_t)(r0 + 8)*1024 + col] = make_float2(acc[im][j8][2] + b0, acc[im][j8][3] + b1);
            }
        }
    } else {
        const int head = bx*2 + wn;                     // 2 heads per N-tile
#pragma unroll
        for (int im = 0; im < 4; im++) {
            const int r0 = m0 + wm*64 + im*16 + (lane >> 2);
            const int b = r0 >> 10, t0 = r0 & 1023, t1 = t0 + 8;
            const size_t d0 = ((size_t)(b*16 + head)*TT + t0)*HDIM;
            const size_t d1 = d0 + 8*HDIM;
            if (do_rope) {
#pragma unroll
                for (int j8 = 0; j8 < 4; j8++) {
                    const int hd = j8*8 + 2*(lane & 3);
                    const float2 ca0 = g_rope[t0*32 + hd];
                    const float2 cb0 = g_rope[t0*32 + hd + 1];
                    const float2 ca1 = g_rope[t1*32 + hd];
                    const float2 cb1 = g_rope[t1*32 + hd + 1];
                    const float xr0 = acc[im][j8][0],   xi0 = acc[im][j8+4][0];
                    const float xr1 = acc[im][j8][1],   xi1 = acc[im][j8+4][1];
                    const float xr2 = acc[im][j8][2],   xi2 = acc[im][j8+4][2];
                    const float xr3 = acc[im][j8][3],   xi3 = acc[im][j8+4][3];
                    *(__half2*)&OH[d0 + hd] = __halves2half2(
                        __float2half_rn(xr0*ca0.x - xi0*ca0.y),
                        __float2half_rn(xr1*cb0.x - xi1*cb0.y));
                    *(__half2*)&OH[d0 + hd + 32] = __halves2half2(
                        __float2half_rn(xr0*ca0.y + xi0*ca0.x),
                        __float2half_rn(xr1*cb0.y + xi1*cb0.x));
                    *(__half2*)&OH[d1 + hd] = __halves2half2(
                        __float2half_rn(xr2*ca1.x - xi2*ca1.y),
                        __float2half_rn(xr3*cb1.x - xi3*cb1.y));
                    *(__half2*)&OH[d1 + hd + 32] = __halves2half2(
                        __float2half_rn(xr2*ca1.y + xi2*ca1.x),
                        __float2half_rn(xr3*cb1.y + xi3*cb1.x));
                }
            } else {
#pragma unroll
                for (int j8 = 0; j8 < 8; j8++) {
                    const int hd = j8*8 + 2*(lane & 3);
                    *(__half2*)&OH[d0 + hd] = __halves2half2(
                        __float2half_rn(acc[im][j8][0]), __float2half_rn(acc[im][j8][1]));
                    *(__half2*)&OH[d1 + hd] = __halves2half2(
                        __float2half_rn(acc[im][j8][2]), __float2half_rn(acc[im][j8][3]));
                }
            }
        }
    }
}

// batched q/k/v GEMM (single-term, K=1024) with fused RoPE/cvt epilogue
__global__ void __launch_bounds__(256, 1) gemm_qkv_kernel() {
    extern __shared__ char smem[];
    const int z = blockIdx.z;
    const __half* A = (z == 0) ? g_qcat : (z == 1) ? g_kcat : g_vcat;
    const __half* W = (z == 0) ? g_wq   : (z == 1) ? g_wk   : g_wv;
    __half*      O = (z == 0) ? g_qh   : (z == 1) ? g_kh   : g_vh;
    gemm_body<DIMN, 16, 1>(A, W, nullptr, nullptr, O, (z < 2) ? 1 : 0,
                           smem, blockIdx.x, blockIdx.y);
}

// proj GEMM (single-term, K=1024)
__global__ void __launch_bounds__(256, 1) gemm_proj_kernel(const float* __restrict__ bias,
                                                           float* __restrict__ out) {
    extern __shared__ char smem[];
    gemm_body<DIMN, 16, 0>(g_acat, g_wp, bias, out, nullptr, 0,
                           smem, blockIdx.x, blockIdx.y);
}

// ---------------- kernel 5: tensor-core causal flash attention (1-seg QK, 1-term PV) --------
#define ATTN_SMEM 40960

__global__ void __launch_bounds__(128, 3) attn_mma_kernel() {
    extern __shared__ char smx[];
    const unsigned int su = (unsigned int)__cvta_generic_to_shared(smx);
    const int tid = threadIdx.x, lane = tid & 31, warp = tid >> 5;
    const int bx = blockIdx.x;
    const int qt = 15 - (bx >> 6);
    const int bh = bx & 63;
    const int q0 = qt * 64;
    const int nk = qt + 1;
    const size_t hb = (size_t)bh * (TT * HDIM);

    auto ldt = [&](unsigned int dstBase, const __half* g, int row0) {
#pragma unroll
        for (int e2 = 0; e2 < 4; e2++) {
            int idx = tid + e2*128;
            int r = idx >> 3, ch = idx & 7;
            cpa16(dstBase + (unsigned int)(r*128 + ((ch ^ (r & 7)) << 4)),
                  g + hb + (size_t)(row0 + r)*HDIM + ch*8);
        }
    };
    auto issue_kv = [&](int kt) {
        unsigned int base = su + 8192u + (unsigned int)((kt & 1) * 16384);
        ldt(base,         g_kh, kt*64);
        ldt(base + 8192u, g_vh, kt*64);
        asm volatile("cp.async.commit_group;\n");
    };

    ldt(su, g_qh, q0);
    asm volatile("cp.async.commit_group;\n");
    issue_kv(0);
    if (nk > 1) { issue_kv(1); asm volatile("cp.async.wait_group 1;\n"); }
    else        {              asm volatile("cp.async.wait_group 0;\n"); }
    __syncthreads();

    const int hi16 = lane >> 4;
    const int krow = lane & 15;
    const int wrow = warp*16 + (lane >> 2);

    unsigned int aq[4][4];
    {
        const int qrow = warp*16 + krow;
#pragma unroll
        for (int ck = 0; ck < 4; ck++)
            ldsm4(su + (unsigned int)(qrow*128 + (((2*ck + hi16) ^ (qrow & 7)) << 4)), aq[ck]);
    }

    float oacc[8][4], lacc[4];
#pragma unroll
    for (int j = 0; j < 8; j++)
#pragma unroll
        for (int e = 0; e < 4; e++) oacc[j][e] = 0.f;
#pragma unroll
    for (int e = 0; e < 4; e++) lacc[e] = 0.f;
    float m0 = -1e30f, m1 = -1e30f;

    const unsigned int ONES = 0x3C003C00u;

    for (int kt = 0; kt < nk; kt++) {
        const unsigned int sb = su + 8192u + (unsigned int)((kt & 1) * 16384);

        float c[8][4];
#pragma unroll
        for (int j = 0; j < 8; j++)
#pragma unroll
            for (int e = 0; e < 4; e++) c[j][e] = 0.f;

        // ---- S = Qh · Kh^T ----
#pragma unroll
        for (int ck = 0; ck < 4; ck++) {
#pragma unroll
            for (int g = 0; g < 4; g++) {
                unsigned int bq[4];
                const int row = g*16 + krow;
                ldsm4(sb + (unsigned int)(row*128 + (((2*ck + hi16) ^ (row & 7)) << 4)), bq);
                mmah(c[2*g],   aq[ck][0], aq[ck][1], aq[ck][2], aq[ck][3], bq[0], bq[2]);
                mmah(c[2*g+1], aq[ck][0], aq[ck][1], aq[ck][2], aq[ck][3], bq[1], bq[3]);
            }
        }

        const float alpha = 0.18033688011112042f;   // 0.125 * log2(e)
#pragma unroll
        for (int j = 0; j < 8; j++) {
            c[j][0] *= alpha; c[j][1] *= alpha; c[j][2] *= alpha; c[j][3] *= alpha;
        }
        if (kt == qt) {
#pragma unroll
            for (int j = 0; j < 8; j++) {
                const int cb = 8*j + 2*(lane & 3);
                if (cb     > wrow)     c[j][0] = -30000.f;
                if (cb + 1 > wrow)     c[j][1] = -30000.f;
                if (cb     > wrow + 8) c[j][2] = -30000.f;
                if (cb + 1 > wrow + 8) c[j][3] = -30000.f;
            }
        }
        float ml0 = -1e30f, ml1 = -1e30f;
#pragma unroll
        for (int j = 0; j < 8; j++) {
            ml0 = fmaxf(ml0, fmaxf(c[j][0], c[j][1]));
            ml1 = fmaxf(ml1, fmaxf(c[j][2], c[j][3]));
        }
#pragma unroll
        for (int off = 1; off <= 2; off <<= 1) {
            ml0 = fmaxf(ml0, __shfl_xor_sync(0xffffffffu, ml0, off));
            ml1 = fmaxf(ml1, __shfl_xor_sync(0xffffffffu, ml1, off));
        }
        const float mn0 = fmaxf(m0, ml0), mn1 = fmaxf(m1, ml1);
        const float cr0 = exp2f(m0 - mn0), cr1 = exp2f(m1 - mn1);
        m0 = mn0; m1 = mn1;

        unsigned int pf[2][8];
#pragma unroll
        for (int j = 0; j < 8; j++) {
            pf[0][j] = ex2h2(cvt2h(c[j][1] - m0, c[j][0] - m0));
            pf[1][j] = ex2h2(cvt2h(c[j][3] - m1, c[j][2] - m1));
        }
#pragma unroll
        for (int j = 0; j < 8; j++) {
            oacc[j][0] *= cr0; oacc[j][1] *= cr0;
            oacc[j][2] *= cr1; oacc[j][3] *= cr1;
        }
        lacc[0] *= cr0; lacc[1] *= cr0; lacc[2] *= cr1; lacc[3] *= cr1;

        // ---- O += P Vh, l += P @ ones ----
        const unsigned int Vb = sb + 8192u;
#pragma unroll
        for (int kc = 0; kc < 4; kc++) {
            const unsigned int a0 = pf[0][2*kc],   a1 = pf[1][2*kc];
            const unsigned int a2 = pf[0][2*kc+1], a3 = pf[1][2*kc+1];
            mmah(lacc, a0, a1, a2, a3, ONES, ONES);
            const int rbase = kc*16 + krow;
#pragma unroll
            for (int jj = 0; jj < 4; jj++) {
                unsigned int bv[4];
                ldsm4t(Vb + (unsigned int)(rbase*128 + (((2*jj + hi16) ^ (rbase & 7)) << 4)), bv);
                mmah(oacc[2*jj],   a0, a1, a2, a3, bv[0], bv[1]);
                mmah(oacc[2*jj+1], a0, a1, a2, a3, bv[2], bv[3]);
            }
        }

        if (kt + 1 < nk) {
            __syncthreads();
            if (kt + 2 < nk) {
                issue_kv(kt + 2);
                asm volatile("cp.async.wait_group 1;\n");
            } else {
                asm volatile("cp.async.wait_group 0;\n");
            }
            __syncthreads();
        }
    }

    // ---- epilogue: write fp16 into g_acat ([tok][1024]) ----
    const float inv0 = 1.f / lacc[0];
    const float inv1 = 1.f / lacc[2];
    const int b = bh >> 4, h = bh & 15;
    const size_t tok0 = (size_t)b*TT + q0 + wrow;
#pragma unroll
    for (int j = 0; j < 8; j++) {
        const int col = 8*j + 2*(lane & 3);
        float a0 = oacc[j][0]*inv0, a1 = oacc[j][1]*inv0;
        float a2 = oacc[j][2]*inv1, a3 = oacc[j][3]*inv1;
        size_t base0 = tok0*DIMN + h*HDIM + col;
        size_t base1 = (tok0 + 8)*DIMN + h*HDIM + col;
        *(__half2*)&g_acat[base0] = __halves2half2(__float2half_rn(a0), __float2half_rn(a1));
        *(__half2*)&g_acat[base1] = __halves2half2(__float2half_rn(a2), __float2half_rn(a3));
    }
}

// ---------------- launch ----------------
extern "C" void kernel_launch(void* const* d_in, const int* in_sizes, int n_in,
                              void* d_out, int out_size) {
    const float* x      = (const float*)d_in[0];
    const float* q_w    = (const float*)d_in[1];
    const float* k_w    = (const float*)d_in[2];
    const float* v_w    = (const float*)d_in[3];
    const float* q_a    = (const float*)d_in[4];
    const float* q_b    = (const float*)d_in[5];
    const float* q_l    = (const float*)d_in[6];
    const float* k_a    = (const float*)d_in[7];
    const float* k_b    = (const float*)d_in[8];
    const float* k_l    = (const float*)d_in[9];
    const float* v_a    = (const float*)d_in[10];
    const float* v_b    = (const float*)d_in[11];
    const float* v_l    = (const float*)d_in[12];
    const float* proj_w = (const float*)d_in[13];
    const float* proj_b = (const float*)d_in[14];
    float* out = (float*)d_out;

    cudaFuncSetAttribute(gemm_qkv_kernel,
                         cudaFuncAttributeMaxDynamicSharedMemorySize, GSMEM);
    cudaFuncSetAttribute(gemm_proj_kernel,
                         cudaFuncAttributeMaxDynamicSharedMemorySize, GSMEM);
    cudaFuncSetAttribute(attn_mma_kernel,
                         cudaFuncAttributeMaxDynamicSharedMemorySize, ATTN_SMEM);

    rope_tab_kernel<<<(TT*32)/256, 256>>>();
    split_w4_kernel<<<dim3((DIMN*DIMN)/256, 4), 256>>>(q_w, k_w, v_w, proj_w);
    lora_h_kernel<<<MTOK/8, 256>>>(x, q_a, k_a, v_a);
    mod_input3_kernel<<<dim3(MTOK/32, 2), 256>>>(x, q_b, q_l, k_b, k_l, v_b, v_l);

    gemm_qkv_kernel<<<dim3(8, 16, 3), 256, GSMEM>>>();

    attn_mma_kernel<<<1024, 128, ATTN_SMEM>>>();

    gemm_proj_kernel<<<dim3(8, 16), 256, GSMEM>>>(proj_b, out);
}